// round 1
// baseline (speedup 1.0000x reference)
#include <cuda_runtime.h>
#include <cuda_bf16.h>
#include <math_constants.h>

// Problem constants: B=2, N=2048, E=1024, H=16, D=64
#define B_  2
#define N_  2048
#define E_  1024
#define H_  16
#define D_  64
#define M_  (B_ * N_)          // 4096 rows for projections

// ---------------------------------------------------------------------------
// Scratch (allocation-free: __device__ globals)
// ---------------------------------------------------------------------------
__device__ float g_Q[M_ * E_];   // [b,n,(h d)] row-major, 16 MB
__device__ float g_K[M_ * E_];
__device__ float g_V[M_ * E_];
__device__ float g_C[M_ * E_];   // attention context, [b,n,(h d)]

// ---------------------------------------------------------------------------
// SGEMM NT + bias:  C[m,n] = sum_k A[m,k] * W[n,k] + bias[n]
// BM=BN=128, BK=8, 256 threads, 8x8 microtile with strided row assignment
// (rows m = 16*i + ty, cols n = 16*j + tx) for conflict-free smem reads.
// ---------------------------------------------------------------------------
#define BM 128
#define BN 128
#define BK 8

__global__ __launch_bounds__(256) void sgemm_nt_bias(
    const float* __restrict__ A, const float* __restrict__ W,
    const float* __restrict__ bias, float* __restrict__ C,
    int M, int Nn, int K)
{
    __shared__ float As[BM][BK + 1];   // pad 9: reads broadcast over ty
    __shared__ float Ws[BN][BK + 1];   // reads: bank = 9*tx + const -> conflict-free

    const int tid = threadIdx.x;
    const int tx = tid & 15;
    const int ty = tid >> 4;
    const int m0 = blockIdx.y * BM;
    const int n0 = blockIdx.x * BN;

    float acc[8][8];
#pragma unroll
    for (int i = 0; i < 8; i++)
#pragma unroll
        for (int j = 0; j < 8; j++) acc[i][j] = 0.0f;

    const int lrow = tid >> 1;          // 0..127
    const int lkc  = (tid & 1) << 2;    // 0 or 4

    for (int k0 = 0; k0 < K; k0 += BK) {
        // Load 128x8 tiles of A and W (one float4 per thread each)
        float4 va = *reinterpret_cast<const float4*>(&A[(size_t)(m0 + lrow) * K + k0 + lkc]);
        float4 vw = *reinterpret_cast<const float4*>(&W[(size_t)(n0 + lrow) * K + k0 + lkc]);
        As[lrow][lkc + 0] = va.x; As[lrow][lkc + 1] = va.y;
        As[lrow][lkc + 2] = va.z; As[lrow][lkc + 3] = va.w;
        Ws[lrow][lkc + 0] = vw.x; Ws[lrow][lkc + 1] = vw.y;
        Ws[lrow][lkc + 2] = vw.z; Ws[lrow][lkc + 3] = vw.w;
        __syncthreads();

#pragma unroll
        for (int k = 0; k < BK; k++) {
            float a[8], b[8];
#pragma unroll
            for (int i = 0; i < 8; i++) a[i] = As[i * 16 + ty][k];
#pragma unroll
            for (int j = 0; j < 8; j++) b[j] = Ws[j * 16 + tx][k];
#pragma unroll
            for (int i = 0; i < 8; i++)
#pragma unroll
                for (int j = 0; j < 8; j++) acc[i][j] = fmaf(a[i], b[j], acc[i][j]);
        }
        __syncthreads();
    }

    // Epilogue
#pragma unroll
    for (int j = 0; j < 8; j++) {
        float bj = bias[n0 + j * 16 + tx];
#pragma unroll
        for (int i = 0; i < 8; i++) {
            C[(size_t)(m0 + i * 16 + ty) * Nn + n0 + j * 16 + tx] = acc[i][j] + bj;
        }
    }
}

// ---------------------------------------------------------------------------
// Flash attention (fp32): per (b, h, q-tile of 64), iterate over KV tiles of 32.
// Reference semantics: energy = q.k (NO pre-scale); softmax over k; then /32.
// Folded into final normalization: o / (l * 32).
// Layouts: Q/K/V/C are [b, n, (h d)] row-major (stride E_ between tokens).
// ---------------------------------------------------------------------------
#define QT 64
#define KT 32

__global__ __launch_bounds__(256) void flash_attn(
    const float* __restrict__ Q, const float* __restrict__ Kg,
    const float* __restrict__ Vg, float* __restrict__ Ctx)
{
    __shared__ float Qs[QT][D_ + 1];    // 64 x 65
    __shared__ float Ks[KT][D_ + 1];    // 32 x 65
    __shared__ float Vs[KT][D_ + 1];    // 32 x 65
    __shared__ float Ps[QT][KT + 1];    // 64 x 33

    const int b  = blockIdx.z;
    const int h  = blockIdx.y;
    const int q0 = blockIdx.x * QT;
    const int tid = threadIdx.x;
    const int tx = tid & 15;
    const int ty = tid >> 4;
    const int cb = h * D_;              // column base within E

    // Load Q tile: 64 x 64 floats = 16 per thread = 4 float4
#pragma unroll
    for (int p = 0; p < 4; p++) {
        int idx = p * 256 + tid;
        int row = idx >> 4;
        int dc  = (idx & 15) << 2;
        float4 v = *reinterpret_cast<const float4*>(
            &Q[(size_t)((b * N_) + q0 + row) * E_ + cb + dc]);
        Qs[row][dc + 0] = v.x; Qs[row][dc + 1] = v.y;
        Qs[row][dc + 2] = v.z; Qs[row][dc + 3] = v.w;
    }

    float m_i[4], l_i[4], o[4][4];
#pragma unroll
    for (int i = 0; i < 4; i++) {
        m_i[i] = -CUDART_INF_F;
        l_i[i] = 0.0f;
#pragma unroll
        for (int j = 0; j < 4; j++) o[i][j] = 0.0f;
    }

    for (int t = 0; t < N_ / KT; t++) {
        __syncthreads();   // previous iteration's Ks/Vs/Ps fully consumed

        // Load K/V tiles: 32 x 64 each = 8 floats per thread = 2 float4 each
#pragma unroll
        for (int p = 0; p < 2; p++) {
            int idx = p * 256 + tid;
            int row = idx >> 4;
            int dc  = (idx & 15) << 2;
            size_t g = (size_t)((b * N_) + t * KT + row) * E_ + cb + dc;
            float4 kv = *reinterpret_cast<const float4*>(&Kg[g]);
            float4 vv = *reinterpret_cast<const float4*>(&Vg[g]);
            Ks[row][dc + 0] = kv.x; Ks[row][dc + 1] = kv.y;
            Ks[row][dc + 2] = kv.z; Ks[row][dc + 3] = kv.w;
            Vs[row][dc + 0] = vv.x; Vs[row][dc + 1] = vv.y;
            Vs[row][dc + 2] = vv.z; Vs[row][dc + 3] = vv.w;
        }
        __syncthreads();

        // S = Q K^T for this tile; thread owns rows 16i+ty, cols 16j+tx (j<2)
        float s[4][2];
#pragma unroll
        for (int i = 0; i < 4; i++) { s[i][0] = 0.0f; s[i][1] = 0.0f; }
#pragma unroll
        for (int d = 0; d < D_; d++) {
            float a[4], bb[2];
#pragma unroll
            for (int i = 0; i < 4; i++) a[i] = Qs[i * 16 + ty][d];
            bb[0] = Ks[tx][d];
            bb[1] = Ks[16 + tx][d];
#pragma unroll
            for (int i = 0; i < 4; i++) {
                s[i][0] = fmaf(a[i], bb[0], s[i][0]);
                s[i][1] = fmaf(a[i], bb[1], s[i][1]);
            }
        }

        // Online softmax per row (16 tx lanes share each row; xor-shuffle over tx bits)
#pragma unroll
        for (int i = 0; i < 4; i++) {
            float tmax = fmaxf(s[i][0], s[i][1]);
#pragma unroll
            for (int msk = 1; msk <= 8; msk <<= 1)
                tmax = fmaxf(tmax, __shfl_xor_sync(0xFFFFFFFFu, tmax, msk));
            float mn = fmaxf(m_i[i], tmax);
            float alpha = __expf(m_i[i] - mn);   // first tile: exp(-inf) = 0
            m_i[i] = mn;
            float p0 = __expf(s[i][0] - mn);
            float p1 = __expf(s[i][1] - mn);
            float ts = p0 + p1;
#pragma unroll
            for (int msk = 1; msk <= 8; msk <<= 1)
                ts += __shfl_xor_sync(0xFFFFFFFFu, ts, msk);
            l_i[i] = l_i[i] * alpha + ts;
#pragma unroll
            for (int j = 0; j < 4; j++) o[i][j] *= alpha;
            Ps[i * 16 + ty][tx]      = p0;
            Ps[i * 16 + ty][16 + tx] = p1;
        }
        __syncthreads();

        // O += P @ V : o[i][j], output cols 16j+tx
#pragma unroll 8
        for (int c = 0; c < KT; c++) {
            float pp[4], vv[4];
#pragma unroll
            for (int i = 0; i < 4; i++) pp[i] = Ps[i * 16 + ty][c];
#pragma unroll
            for (int j = 0; j < 4; j++) vv[j] = Vs[c][j * 16 + tx];
#pragma unroll
            for (int i = 0; i < 4; i++)
#pragma unroll
                for (int j = 0; j < 4; j++) o[i][j] = fmaf(pp[i], vv[j], o[i][j]);
        }
    }

    // Epilogue: normalize by l (softmax) and by 32 (= sqrt(E), applied AFTER softmax)
#pragma unroll
    for (int i = 0; i < 4; i++) {
        float inv = 1.0f / (l_i[i] * 32.0f);
#pragma unroll
        for (int j = 0; j < 4; j++) {
            Ctx[(size_t)((b * N_) + q0 + i * 16 + ty) * E_ + cb + j * 16 + tx] = o[i][j] * inv;
        }
    }
}

// ---------------------------------------------------------------------------
// kernel_launch: 3 projection GEMMs -> flash attention -> output GEMM.
// All launches on the default stream, in order; graph-capturable; no allocs.
// ---------------------------------------------------------------------------
extern "C" void kernel_launch(void* const* d_in, const int* in_sizes, int n_in,
                              void* d_out, int out_size)
{
    const float* x  = (const float*)d_in[0];
    const float* Wq = (const float*)d_in[1];
    const float* bq = (const float*)d_in[2];
    const float* Wk = (const float*)d_in[3];
    const float* bk = (const float*)d_in[4];
    const float* Wv = (const float*)d_in[5];
    const float* bv = (const float*)d_in[6];
    const float* Wo = (const float*)d_in[7];
    const float* bo = (const float*)d_in[8];
    float* out = (float*)d_out;

    float *Qp, *Kp, *Vp, *Cp;
    cudaGetSymbolAddress((void**)&Qp, g_Q);
    cudaGetSymbolAddress((void**)&Kp, g_K);
    cudaGetSymbolAddress((void**)&Vp, g_V);
    cudaGetSymbolAddress((void**)&Cp, g_C);

    dim3 gemm_grid(E_ / BN, M_ / BM);   // (8, 32)
    sgemm_nt_bias<<<gemm_grid, 256>>>(x, Wq, bq, Qp, M_, E_, E_);
    sgemm_nt_bias<<<gemm_grid, 256>>>(x, Wk, bk, Kp, M_, E_, E_);
    sgemm_nt_bias<<<gemm_grid, 256>>>(x, Wv, bv, Vp, M_, E_, E_);

    dim3 attn_grid(N_ / QT, H_, B_);    // (32, 16, 2)
    flash_attn<<<attn_grid, 256>>>(Qp, Kp, Vp, Cp);

    sgemm_nt_bias<<<gemm_grid, 256>>>(Cp, Wo, bo, out, M_, E_, E_);
}

// round 4
// speedup vs baseline: 2.9485x; 2.9485x over previous
#include <cuda_runtime.h>
#include <cuda_bf16.h>
#include <math_constants.h>
#include <cstdint>

#define B_  2
#define N_  2048
#define E_  1024
#define H_  16
#define D_  64
#define M_  (B_ * N_)
#define K3_ 3072

// ---------------- scratch ----------------
__device__ float g_Q[M_ * E_];
__device__ float g_K[M_ * E_];
__device__ float g_V[M_ * E_];
__device__ float g_C[M_ * E_];
__device__ __nv_bfloat16 g_xext[M_ * K3_];
__device__ __nv_bfloat16 g_cext[M_ * K3_];
__device__ __nv_bfloat16 g_wqext[E_ * K3_];
__device__ __nv_bfloat16 g_wkext[E_ * K3_];
__device__ __nv_bfloat16 g_wvext[E_ * K3_];
__device__ __nv_bfloat16 g_woext[E_ * K3_];

// ---------------- helpers (sm_80-era PTX only) ----------------
__device__ __forceinline__ uint32_t smem_u32(const void* p) {
    uint32_t a;
    asm("{ .reg .u64 t; cvta.to.shared.u64 t, %1; cvt.u32.u64 %0, t; }" : "=r"(a) : "l"(p));
    return a;
}
__device__ __forceinline__ void mma16816(float* c, const uint32_t* a, const uint32_t* b) {
    asm volatile(
        "mma.sync.aligned.m16n8k16.row.col.f32.bf16.bf16.f32 "
        "{%0,%1,%2,%3}, {%4,%5,%6,%7}, {%8,%9}, {%0,%1,%2,%3};"
        : "+f"(c[0]), "+f"(c[1]), "+f"(c[2]), "+f"(c[3])
        : "r"(a[0]), "r"(a[1]), "r"(a[2]), "r"(a[3]), "r"(b[0]), "r"(b[1]));
}
__device__ __forceinline__ void ldsm4t(uint32_t* r, uint32_t addr) {
    asm volatile("ldmatrix.sync.aligned.m8n8.x4.trans.shared.b16 {%0,%1,%2,%3}, [%4];"
        : "=r"(r[0]), "=r"(r[1]), "=r"(r[2]), "=r"(r[3]) : "r"(addr));
}
__device__ __forceinline__ void cp_async8(uint32_t s, const void* g) {
    asm volatile("cp.async.ca.shared.global [%0], [%1], 8;" :: "r"(s), "l"(g) : "memory");
}
__device__ __forceinline__ void cp_commit() {
    asm volatile("cp.async.commit_group;" ::: "memory");
}
__device__ __forceinline__ void pack_hl(float x, float y, uint32_t& hi, uint32_t& lo) {
    __nv_bfloat162 h2 = __floats2bfloat162_rn(x, y);
    float rx = x - __bfloat162float(h2.x);
    float ry = y - __bfloat162float(h2.y);
    __nv_bfloat162 l2 = __floats2bfloat162_rn(rx, ry);
    hi = *reinterpret_cast<uint32_t*>(&h2);
    lo = *reinterpret_cast<uint32_t*>(&l2);
}

// ---------------- split conversion fp32[r x 1024] -> bf16[r x 3072] ----------------
// wmode=0: [hi|lo|hi] (activations)   wmode=1: [hi|hi|lo] (weights)
__global__ __launch_bounds__(256) void cvt_split(
    const float* __restrict__ in, __nv_bfloat16* __restrict__ out, int total_quads, int wmode)
{
    int idx = blockIdx.x * 256 + threadIdx.x;
    if (idx >= total_quads) return;
    int r = idx >> 8;
    int c = (idx & 255) << 2;
    float4 v = *reinterpret_cast<const float4*>(in + (size_t)r * E_ + c);
    uint32_t h0, l0, h1, l1;
    pack_hl(v.x, v.y, h0, l0);
    pack_hl(v.z, v.w, h1, l1);
    uint32_t* o = reinterpret_cast<uint32_t*>(out + (size_t)r * K3_);
    int cw = c >> 1;
    o[cw] = h0; o[cw + 1] = h1;
    if (wmode) { o[512 + cw] = h0; o[512 + cw + 1] = h1; o[1024 + cw] = l0; o[1024 + cw + 1] = l1; }
    else       { o[512 + cw] = l0; o[512 + cw + 1] = l1; o[1024 + cw] = h0; o[1024 + cw + 1] = h1; }
}

// ---------------- HMMA NT GEMM: C[m,n] = sum_k A[m,k] W[n,k] + bias[n] ----------------
// CTA 128x128, BK=32 bf16, 8 warps (4m x 2n), warp m32 x n64, 3-stage cp.async.
#define GS_W 20
#define G_STAGE_W (256 * GS_W)
#define G_SMEM_BYTES (3 * G_STAGE_W * 4)

__global__ __launch_bounds__(256) void gemm_mma(
    const __nv_bfloat16* __restrict__ A, const __nv_bfloat16* __restrict__ W,
    const float* __restrict__ bias, float* __restrict__ C)
{
    extern __shared__ uint32_t smw[];
    const int tid = threadIdx.x;
    const int wid = tid >> 5, lane = tid & 31;
    const int g = lane >> 2, t4 = lane & 3;
    const int wm = wid & 3, wn = wid >> 2;
    const int m0 = blockIdx.y * 128;
    const int n0 = blockIdx.x * 128;
    const int NT = K3_ / 32;   // 96
    const uint32_t smb = smem_u32(smw);

    auto issue = [&](int kt) {
        const int sb = (kt % 3) * G_STAGE_W;
#pragma unroll
        for (int u = 0; u < 4; u++) {
            int c = tid + 256 * u;
            int row = c >> 3, kc = c & 7;
            uint32_t sa = smb + (sb + row * GS_W + kc * 2) * 4;
            cp_async8(sa, A + (size_t)(m0 + row) * K3_ + kt * 32 + kc * 4);
            cp_async8(sa + 128 * GS_W * 4, W + (size_t)(n0 + row) * K3_ + kt * 32 + kc * 4);
        }
        cp_commit();
    };

    float acc[2][8][4];
#pragma unroll
    for (int i = 0; i < 2; i++)
#pragma unroll
        for (int j = 0; j < 8; j++)
#pragma unroll
            for (int q = 0; q < 4; q++) acc[i][j][q] = 0.0f;

    issue(0);
    issue(1);

    for (int kt = 0; kt < NT; kt++) {
        if (kt < NT - 1) asm volatile("cp.async.wait_group 1;" ::: "memory");
        else             asm volatile("cp.async.wait_group 0;" ::: "memory");
        __syncthreads();
        if (kt + 2 < NT) issue(kt + 2);

        const int sb = (kt % 3) * G_STAGE_W;
        const int bb = sb + 128 * GS_W;
#pragma unroll
        for (int kk = 0; kk < 2; kk++) {
            uint32_t a[2][4], b[8][2];
#pragma unroll
            for (int i = 0; i < 2; i++) {
                int r = 32 * wm + 16 * i + g;
                a[i][0] = smw[sb + r * GS_W + 8 * kk + t4];
                a[i][1] = smw[sb + (r + 8) * GS_W + 8 * kk + t4];
                a[i][2] = smw[sb + r * GS_W + 8 * kk + 4 + t4];
                a[i][3] = smw[sb + (r + 8) * GS_W + 8 * kk + 4 + t4];
            }
#pragma unroll
            for (int j = 0; j < 8; j++) {
                int n = 64 * wn + 8 * j + g;
                b[j][0] = smw[bb + n * GS_W + 8 * kk + t4];
                b[j][1] = smw[bb + n * GS_W + 8 * kk + 4 + t4];
            }
#pragma unroll
            for (int i = 0; i < 2; i++)
#pragma unroll
                for (int j = 0; j < 8; j++) mma16816(acc[i][j], a[i], b[j]);
        }
    }

#pragma unroll
    for (int i = 0; i < 2; i++) {
        int row = m0 + 32 * wm + 16 * i + g;
#pragma unroll
        for (int j = 0; j < 8; j++) {
            int col = n0 + 64 * wn + 8 * j + 2 * t4;
            float2 bb2 = *reinterpret_cast<const float2*>(bias + col);
            float2 v0 = { acc[i][j][0] + bb2.x, acc[i][j][1] + bb2.y };
            float2 v1 = { acc[i][j][2] + bb2.x, acc[i][j][3] + bb2.y };
            *reinterpret_cast<float2*>(C + (size_t)row * E_ + col) = v0;
            *reinterpret_cast<float2*>(C + (size_t)(row + 8) * E_ + col) = v1;
        }
    }
}

// ---------------- Flash attention, HMMA, split-bf16 ----------------
// QT=128 (4 warps x m32), KT=64. smem (words):
//  Qs rows 0..127: [Qh 32w | Ql 32w | pad 4w]  stride 68
//  Ks rows 0..63 at KS_BASE: same layout
//  Vs at VS_BASE: rows 0..63 Vh, rows 64..127 Vl, stride 36 ([32w d | 4w pad])
#define FQT 128
#define FKT 64
#define QS_W 68
#define VS_W 36
#define KS_BASE (128 * QS_W)
#define VS_BASE (KS_BASE + 64 * QS_W)
#define F_SMEM_BYTES ((VS_BASE + 128 * VS_W) * 4)

__global__ __launch_bounds__(128) void flash_mma(
    const float* __restrict__ Q, const float* __restrict__ Kg,
    const float* __restrict__ Vg, float* __restrict__ Ctx)
{
    extern __shared__ uint32_t smw[];
    const uint32_t smb = smem_u32(smw);
    const int tid = threadIdx.x;
    const int wid = tid >> 5, lane = tid & 31;
    const int g = lane >> 2, t4 = lane & 3;
    const int bz = blockIdx.z, hh = blockIdx.y;
    const int q0 = blockIdx.x * FQT;
    const size_t gq0 = (size_t)(bz * N_ + q0) * E_ + hh * 64;

    // load + split Q (128 x 64 fp32)
#pragma unroll
    for (int it = 0; it < 32; it++) {
        int idx = tid + 128 * it;
        int row = idx >> 5, d2 = idx & 31;
        float2 v = *reinterpret_cast<const float2*>(Q + gq0 + (size_t)row * E_ + 2 * d2);
        uint32_t hi, lo; pack_hl(v.x, v.y, hi, lo);
        smw[row * QS_W + d2] = hi;
        smw[row * QS_W + 32 + d2] = lo;
    }

    float o[2][8][4], mrow[2][2], lrow[2][2];
#pragma unroll
    for (int i = 0; i < 2; i++) {
        mrow[i][0] = mrow[i][1] = -CUDART_INF_F;
        lrow[i][0] = lrow[i][1] = 0.0f;
#pragma unroll
        for (int j = 0; j < 8; j++)
#pragma unroll
            for (int q = 0; q < 4; q++) o[i][j][q] = 0.0f;
    }

    const int kwq[12] = {0,8,16,24, 32,40,48,56, 0,8,16,24};     // Qh,Ql,Qh
    const int kwk[12] = {0,8,16,24, 0,8,16,24, 32,40,48,56};     // Kh,Kh,Kl
    const int vrm[12] = {0,16,32,48, 0,16,32,48, 64,80,96,112};  // Vh,Vh,Vl

    for (int t = 0; t < N_ / FKT; t++) {
        __syncthreads();
        const size_t gk0 = (size_t)(bz * N_ + t * FKT) * E_ + hh * 64;
#pragma unroll
        for (int it = 0; it < 16; it++) {
            int idx = tid + 128 * it;
            int row = idx >> 5, d2 = idx & 31;
            float2 kv = *reinterpret_cast<const float2*>(Kg + gk0 + (size_t)row * E_ + 2 * d2);
            uint32_t hi, lo; pack_hl(kv.x, kv.y, hi, lo);
            smw[KS_BASE + row * QS_W + d2] = hi;
            smw[KS_BASE + row * QS_W + 32 + d2] = lo;
            float2 vv = *reinterpret_cast<const float2*>(Vg + gk0 + (size_t)row * E_ + 2 * d2);
            pack_hl(vv.x, vv.y, hi, lo);
            smw[VS_BASE + row * VS_W + d2] = hi;
            smw[VS_BASE + (64 + row) * VS_W + d2] = lo;
        }
        __syncthreads();

        // S = Q Kt (12 split k-steps)
        float s[2][8][4];
#pragma unroll
        for (int i = 0; i < 2; i++)
#pragma unroll
            for (int j = 0; j < 8; j++)
#pragma unroll
                for (int q = 0; q < 4; q++) s[i][j][q] = 0.0f;
#pragma unroll
        for (int kp = 0; kp < 12; kp++) {
            uint32_t a[2][4], b[8][2];
            const int qw = kwq[kp], kw = kwk[kp];
#pragma unroll
            for (int i = 0; i < 2; i++) {
                int r = 32 * wid + 16 * i + g;
                a[i][0] = smw[r * QS_W + qw + t4];
                a[i][1] = smw[(r + 8) * QS_W + qw + t4];
                a[i][2] = smw[r * QS_W + qw + 4 + t4];
                a[i][3] = smw[(r + 8) * QS_W + qw + 4 + t4];
            }
#pragma unroll
            for (int j = 0; j < 8; j++) {
                int n = 8 * j + g;
                b[j][0] = smw[KS_BASE + n * QS_W + kw + t4];
                b[j][1] = smw[KS_BASE + n * QS_W + kw + 4 + t4];
            }
#pragma unroll
            for (int i = 0; i < 2; i++)
#pragma unroll
                for (int j = 0; j < 8; j++) mma16816(s[i][j], a[i], b[j]);
        }

        // online softmax (h=0: rows g, h=1: rows g+8)
#pragma unroll
        for (int i = 0; i < 2; i++) {
#pragma unroll
            for (int h = 0; h < 2; h++) {
                float mx = -CUDART_INF_F;
#pragma unroll
                for (int j = 0; j < 8; j++)
                    mx = fmaxf(mx, fmaxf(s[i][j][2 * h], s[i][j][2 * h + 1]));
                mx = fmaxf(mx, __shfl_xor_sync(0xFFFFFFFFu, mx, 1));
                mx = fmaxf(mx, __shfl_xor_sync(0xFFFFFFFFu, mx, 2));
                float mnew = fmaxf(mrow[i][h], mx);
                float alpha = __expf(mrow[i][h] - mnew);
                mrow[i][h] = mnew;
                float ls = 0.0f;
#pragma unroll
                for (int j = 0; j < 8; j++) {
                    float p0 = __expf(s[i][j][2 * h] - mnew);
                    float p1 = __expf(s[i][j][2 * h + 1] - mnew);
                    ls += p0 + p1;
                    s[i][j][2 * h] = p0; s[i][j][2 * h + 1] = p1;
                }
                ls += __shfl_xor_sync(0xFFFFFFFFu, ls, 1);
                ls += __shfl_xor_sync(0xFFFFFFFFu, ls, 2);
                lrow[i][h] = lrow[i][h] * alpha + ls;
#pragma unroll
                for (int j = 0; j < 8; j++) {
                    o[i][j][2 * h] *= alpha; o[i][j][2 * h + 1] *= alpha;
                }
            }
        }

        // pack P hi/lo: C-fragment -> A-fragment remap
        uint32_t ph[2][8], phB[2][8], pl[2][8], plB[2][8];
#pragma unroll
        for (int i = 0; i < 2; i++)
#pragma unroll
            for (int j = 0; j < 8; j++) {
                pack_hl(s[i][j][0], s[i][j][1], ph[i][j], pl[i][j]);
                pack_hl(s[i][j][2], s[i][j][3], phB[i][j], plB[i][j]);
            }

        // O += P V (12 split k-steps over keys)
#pragma unroll
        for (int kp = 0; kp < 12; kp++) {
            const int vr = vrm[kp];
            const bool use_lo = (kp >= 4) && (kp < 8);
            const int j0 = 2 * (kp & 3);
            uint32_t vb[8][2];
#pragma unroll
            for (int jj = 0; jj < 8; jj += 2) {
                uint32_t r4[4];
                int tsel = lane >> 3;
                int row = vr + 8 * (tsel & 1) + (lane & 7);
                uint32_t addr = smb + VS_BASE * 4 + row * (VS_W * 4) + 16 * (jj + (tsel >> 1));
                ldsm4t(r4, addr);
                vb[jj][0] = r4[0]; vb[jj][1] = r4[1];
                vb[jj + 1][0] = r4[2]; vb[jj + 1][1] = r4[3];
            }
#pragma unroll
            for (int i = 0; i < 2; i++) {
                uint32_t pa[4];
                pa[0] = use_lo ? pl[i][j0]      : ph[i][j0];
                pa[1] = use_lo ? plB[i][j0]     : phB[i][j0];
                pa[2] = use_lo ? pl[i][j0 + 1]  : ph[i][j0 + 1];
                pa[3] = use_lo ? plB[i][j0 + 1] : phB[i][j0 + 1];
#pragma unroll
                for (int j = 0; j < 8; j++) mma16816(o[i][j], pa, vb[j]);
            }
        }
    }

    // out = o / (l * 32)   (reference: softmax first, then /sqrt(E))
#pragma unroll
    for (int i = 0; i < 2; i++) {
        float inv0 = 1.0f / (lrow[i][0] * 32.0f);
        float inv1 = 1.0f / (lrow[i][1] * 32.0f);
        int row = bz * N_ + q0 + 32 * wid + 16 * i + g;
#pragma unroll
        for (int j = 0; j < 8; j++) {
            int col = hh * 64 + 8 * j + 2 * t4;
            float2 v0 = { o[i][j][0] * inv0, o[i][j][1] * inv0 };
            float2 v1 = { o[i][j][2] * inv1, o[i][j][3] * inv1 };
            *reinterpret_cast<float2*>(Ctx + (size_t)row * E_ + col) = v0;
            *reinterpret_cast<float2*>(Ctx + (size_t)(row + 8) * E_ + col) = v1;
        }
    }
}

// ---------------- launcher ----------------
extern "C" void kernel_launch(void* const* d_in, const int* in_sizes, int n_in,
                              void* d_out, int out_size)
{
    const float* x  = (const float*)d_in[0];
    const float* Wq = (const float*)d_in[1];
    const float* bq = (const float*)d_in[2];
    const float* Wk = (const float*)d_in[3];
    const float* bk = (const float*)d_in[4];
    const float* Wv = (const float*)d_in[5];
    const float* bv = (const float*)d_in[6];
    const float* Wo = (const float*)d_in[7];
    const float* bo = (const float*)d_in[8];
    float* out = (float*)d_out;

    cudaFuncSetAttribute(gemm_mma,  cudaFuncAttributeMaxDynamicSharedMemorySize, G_SMEM_BYTES);
    cudaFuncSetAttribute(flash_mma, cudaFuncAttributeMaxDynamicSharedMemorySize, F_SMEM_BYTES);

    float *Qp, *Kp, *Vp, *Cp;
    __nv_bfloat16 *xe, *ce, *wqe, *wke, *wve, *woe;
    cudaGetSymbolAddress((void**)&Qp, g_Q);
    cudaGetSymbolAddress((void**)&Kp, g_K);
    cudaGetSymbolAddress((void**)&Vp, g_V);
    cudaGetSymbolAddress((void**)&Cp, g_C);
    cudaGetSymbolAddress((void**)&xe, g_xext);
    cudaGetSymbolAddress((void**)&ce, g_cext);
    cudaGetSymbolAddress((void**)&wqe, g_wqext);
    cudaGetSymbolAddress((void**)&wke, g_wkext);
    cudaGetSymbolAddress((void**)&wve, g_wvext);
    cudaGetSymbolAddress((void**)&woe, g_woext);

    cvt_split<<<M_, 256>>>(x,  xe,  M_ * 256, 0);
    cvt_split<<<E_, 256>>>(Wq, wqe, E_ * 256, 1);
    cvt_split<<<E_, 256>>>(Wk, wke, E_ * 256, 1);
    cvt_split<<<E_, 256>>>(Wv, wve, E_ * 256, 1);
    cvt_split<<<E_, 256>>>(Wo, woe, E_ * 256, 1);

    dim3 ggrid(E_ / 128, M_ / 128);     // (8, 32)
    gemm_mma<<<ggrid, 256, G_SMEM_BYTES>>>(xe, wqe, bq, Qp);
    gemm_mma<<<ggrid, 256, G_SMEM_BYTES>>>(xe, wke, bk, Kp);
    gemm_mma<<<ggrid, 256, G_SMEM_BYTES>>>(xe, wve, bv, Vp);

    dim3 fgrid(N_ / FQT, H_, B_);       // (16, 16, 2)
    flash_mma<<<fgrid, 128, F_SMEM_BYTES>>>(Qp, Kp, Vp, Cp);

    cvt_split<<<M_, 256>>>(Cp, ce, M_ * 256, 0);
    gemm_mma<<<ggrid, 256, G_SMEM_BYTES>>>(ce, woe, bo, out);
}

// round 5
// speedup vs baseline: 3.2747x; 1.1106x over previous
#include <cuda_runtime.h>
#include <cuda_bf16.h>
#include <math_constants.h>
#include <cstdint>

#define B_  2
#define N_  2048
#define E_  1024
#define H_  16
#define D_  64
#define M_  (B_ * N_)
#define K3_ 3072

// ---------------- scratch ----------------
// Q/K/V stored pre-split: [row][head][64 hi | 64 lo] bf16  (2048 bf16 per row)
__device__ __nv_bfloat16 g_Qs[M_ * 2048];
__device__ __nv_bfloat16 g_Ks[M_ * 2048];
__device__ __nv_bfloat16 g_Vs[M_ * 2048];
__device__ __nv_bfloat16 g_xext[M_ * K3_];     // [hi|lo|hi]
__device__ __nv_bfloat16 g_cext[M_ * K3_];     // [hi|lo|hi], written by flash
__device__ __nv_bfloat16 g_wqext[E_ * K3_];    // [hi|hi|lo]
__device__ __nv_bfloat16 g_wkext[E_ * K3_];
__device__ __nv_bfloat16 g_wvext[E_ * K3_];
__device__ __nv_bfloat16 g_woext[E_ * K3_];

// ---------------- helpers ----------------
__device__ __forceinline__ uint32_t smem_u32(const void* p) {
    uint32_t a;
    asm("{ .reg .u64 t; cvta.to.shared.u64 t, %1; cvt.u32.u64 %0, t; }" : "=r"(a) : "l"(p));
    return a;
}
__device__ __forceinline__ void mma16816(float* c, const uint32_t* a, const uint32_t* b) {
    asm volatile(
        "mma.sync.aligned.m16n8k16.row.col.f32.bf16.bf16.f32 "
        "{%0,%1,%2,%3}, {%4,%5,%6,%7}, {%8,%9}, {%0,%1,%2,%3};"
        : "+f"(c[0]), "+f"(c[1]), "+f"(c[2]), "+f"(c[3])
        : "r"(a[0]), "r"(a[1]), "r"(a[2]), "r"(a[3]), "r"(b[0]), "r"(b[1]));
}
__device__ __forceinline__ void ldsm4(uint32_t* r, uint32_t addr) {
    asm volatile("ldmatrix.sync.aligned.m8n8.x4.shared.b16 {%0,%1,%2,%3}, [%4];"
        : "=r"(r[0]), "=r"(r[1]), "=r"(r[2]), "=r"(r[3]) : "r"(addr));
}
__device__ __forceinline__ void ldsm4t(uint32_t* r, uint32_t addr) {
    asm volatile("ldmatrix.sync.aligned.m8n8.x4.trans.shared.b16 {%0,%1,%2,%3}, [%4];"
        : "=r"(r[0]), "=r"(r[1]), "=r"(r[2]), "=r"(r[3]) : "r"(addr));
}
__device__ __forceinline__ void cp_async16(uint32_t s, const void* g) {
    asm volatile("cp.async.cg.shared.global [%0], [%1], 16;" :: "r"(s), "l"(g) : "memory");
}
__device__ __forceinline__ void cp_commit() {
    asm volatile("cp.async.commit_group;" ::: "memory");
}
__device__ __forceinline__ void pack_hl(float x, float y, uint32_t& hi, uint32_t& lo) {
    __nv_bfloat162 h2 = __floats2bfloat162_rn(x, y);
    float rx = x - __bfloat162float(h2.x);
    float ry = y - __bfloat162float(h2.y);
    __nv_bfloat162 l2 = __floats2bfloat162_rn(rx, ry);
    hi = *reinterpret_cast<uint32_t*>(&h2);
    lo = *reinterpret_cast<uint32_t*>(&l2);
}

// ---------------- x conversion: fp32[r x 1024] -> bf16[r x 3072] [hi|lo|hi] ----------------
__global__ __launch_bounds__(256) void cvt_x(
    const float* __restrict__ in, __nv_bfloat16* __restrict__ out)
{
    int idx = blockIdx.x * 256 + threadIdx.x;
    int r = idx >> 8;
    int c = (idx & 255) << 2;
    float4 v = *reinterpret_cast<const float4*>(in + (size_t)r * E_ + c);
    uint32_t h0, l0, h1, l1;
    pack_hl(v.x, v.y, h0, l0);
    pack_hl(v.z, v.w, h1, l1);
    uint32_t* o = reinterpret_cast<uint32_t*>(out + (size_t)r * K3_);
    int cw = c >> 1;
    o[cw] = h0; o[cw + 1] = h1;
    o[512 + cw] = l0; o[512 + cw + 1] = l1;
    o[1024 + cw] = h0; o[1024 + cw + 1] = h1;
}

// ---------------- weight conversion (4 weights fused): [hi|hi|lo] ----------------
__global__ __launch_bounds__(256) void cvt_w4(
    const float* __restrict__ W0, const float* __restrict__ W1,
    const float* __restrict__ W2, const float* __restrict__ W3,
    __nv_bfloat16* __restrict__ O0, __nv_bfloat16* __restrict__ O1,
    __nv_bfloat16* __restrict__ O2, __nv_bfloat16* __restrict__ O3)
{
    int sel = blockIdx.y;
    const float* in = sel == 0 ? W0 : sel == 1 ? W1 : sel == 2 ? W2 : W3;
    __nv_bfloat16* out = sel == 0 ? O0 : sel == 1 ? O1 : sel == 2 ? O2 : O3;
    int idx = blockIdx.x * 256 + threadIdx.x;
    int r = idx >> 8;
    int c = (idx & 255) << 2;
    float4 v = *reinterpret_cast<const float4*>(in + (size_t)r * E_ + c);
    uint32_t h0, l0, h1, l1;
    pack_hl(v.x, v.y, h0, l0);
    pack_hl(v.z, v.w, h1, l1);
    uint32_t* o = reinterpret_cast<uint32_t*>(out + (size_t)r * K3_);
    int cw = c >> 1;
    o[cw] = h0; o[cw + 1] = h1;
    o[512 + cw] = h0;  o[512 + cw + 1] = h1;
    o[1024 + cw] = l0; o[1024 + cw + 1] = l1;
}

// ---------------- HMMA NT GEMM (ldmatrix), templated epilogue ----------------
// CTA 128x128, BK=32, 8 warps (4m x 2n), 3-stage cp.async, smem stride 20 words.
// SPLIT=1: out = per-head bf16 [row][head][64hi|64lo]  (QKV; blockIdx.z selects W/bias/out)
// SPLIT=0: out = fp32 C[row][1024] + bias
#define GS_W 20
#define G_STAGE_W (256 * GS_W)
#define G_SMEM_BYTES (3 * G_STAGE_W * 4)

template<int SPLIT>
__global__ __launch_bounds__(256) void gemm_mma_t(
    const __nv_bfloat16* __restrict__ A,
    const __nv_bfloat16* __restrict__ W0, const __nv_bfloat16* __restrict__ W1,
    const __nv_bfloat16* __restrict__ W2,
    const float* __restrict__ b0, const float* __restrict__ b1, const float* __restrict__ b2,
    float* __restrict__ Cf,
    __nv_bfloat16* __restrict__ S0, __nv_bfloat16* __restrict__ S1,
    __nv_bfloat16* __restrict__ S2)
{
    extern __shared__ uint32_t smw[];
    const int z = blockIdx.z;
    const __nv_bfloat16* W = (z == 0) ? W0 : (z == 1) ? W1 : W2;
    const float* bias = (z == 0) ? b0 : (z == 1) ? b1 : b2;
    __nv_bfloat16* Sp = (z == 0) ? S0 : (z == 1) ? S1 : S2;

    const int tid = threadIdx.x;
    const int wid = tid >> 5, lane = tid & 31;
    const int g = lane >> 2, t4 = lane & 3;
    const int wm = wid & 3, wn = wid >> 2;
    const int m0 = blockIdx.y * 128;
    const int n0 = blockIdx.x * 128;
    const int NT = K3_ / 32;   // 96
    const uint32_t smb = smem_u32(smw);

    auto issue = [&](int kt) {
        const int sb = (kt % 3) * G_STAGE_W;
#pragma unroll
        for (int u = 0; u < 2; u++) {
            int c = tid + 256 * u;           // 0..511
            int row = c >> 2, k4 = c & 3;
            uint32_t sa = smb + (sb + row * GS_W + k4 * 4) * 4;
            cp_async16(sa, A + (size_t)(m0 + row) * K3_ + kt * 32 + k4 * 8);
            cp_async16(sa + 128 * GS_W * 4, W + (size_t)(n0 + row) * K3_ + kt * 32 + k4 * 8);
        }
        cp_commit();
    };

    float acc[2][8][4];
#pragma unroll
    for (int i = 0; i < 2; i++)
#pragma unroll
        for (int j = 0; j < 8; j++)
#pragma unroll
            for (int q = 0; q < 4; q++) acc[i][j][q] = 0.0f;

    issue(0);
    issue(1);

    // ldmatrix lane addressing (constant per thread)
    const int a_row = 32 * wm + (lane & 15);       // + 16*i
    const int a_cw  = 4 * (lane >> 4);             // + 8*kk
    const int b_row = 64 * wn + (lane & 7) + 8 * (lane >> 4);   // + 16*jp
    const int b_cw  = 4 * ((lane >> 3) & 1);       // + 8*kk

    for (int kt = 0; kt < NT; kt++) {
        if (kt < NT - 1) asm volatile("cp.async.wait_group 1;" ::: "memory");
        else             asm volatile("cp.async.wait_group 0;" ::: "memory");
        __syncthreads();
        if (kt + 2 < NT) issue(kt + 2);

        const int sb = (kt % 3) * G_STAGE_W;
        const int bb = sb + 128 * GS_W;
#pragma unroll
        for (int kk = 0; kk < 2; kk++) {
            uint32_t a[2][4], b[8][2];
#pragma unroll
            for (int i = 0; i < 2; i++)
                ldsm4(a[i], smb + (sb + (a_row + 16 * i) * GS_W + a_cw + 8 * kk) * 4);
#pragma unroll
            for (int jp = 0; jp < 4; jp++) {
                uint32_t r4[4];
                ldsm4(r4, smb + (bb + (b_row + 16 * jp) * GS_W + b_cw + 8 * kk) * 4);
                b[2 * jp][0] = r4[0]; b[2 * jp][1] = r4[1];
                b[2 * jp + 1][0] = r4[2]; b[2 * jp + 1][1] = r4[3];
            }
#pragma unroll
            for (int i = 0; i < 2; i++)
#pragma unroll
                for (int j = 0; j < 8; j++) mma16816(acc[i][j], a[i], b[j]);
        }
    }

    if (SPLIT) {
        // per-head bf16 hi/lo: word idx = row*1024 + head*64 + d/2 ; lo at +32
        const int head = (n0 + 64 * wn) >> 6;
        uint32_t* outw = reinterpret_cast<uint32_t*>(Sp);
#pragma unroll
        for (int i = 0; i < 2; i++) {
            int row = m0 + 32 * wm + 16 * i + g;
#pragma unroll
            for (int j = 0; j < 8; j++) {
                int d = 8 * j + 2 * t4;
                float2 bb2 = *reinterpret_cast<const float2*>(bias + n0 + 64 * wn + d);
                uint32_t hi, lo;
                int w0 = row * 1024 + head * 64 + (d >> 1);
                pack_hl(acc[i][j][0] + bb2.x, acc[i][j][1] + bb2.y, hi, lo);
                outw[w0] = hi; outw[w0 + 32] = lo;
                w0 += 8 * 1024;
                pack_hl(acc[i][j][2] + bb2.x, acc[i][j][3] + bb2.y, hi, lo);
                outw[w0] = hi; outw[w0 + 32] = lo;
            }
        }
    } else {
#pragma unroll
        for (int i = 0; i < 2; i++) {
            int row = m0 + 32 * wm + 16 * i + g;
#pragma unroll
            for (int j = 0; j < 8; j++) {
                int col = n0 + 64 * wn + 8 * j + 2 * t4;
                float2 bb2 = *reinterpret_cast<const float2*>(bias + col);
                float2 v0 = { acc[i][j][0] + bb2.x, acc[i][j][1] + bb2.y };
                float2 v1 = { acc[i][j][2] + bb2.x, acc[i][j][3] + bb2.y };
                *reinterpret_cast<float2*>(Cf + (size_t)row * E_ + col) = v0;
                *reinterpret_cast<float2*>(Cf + (size_t)(row + 8) * E_ + col) = v1;
            }
        }
    }
}

// ---------------- Flash attention (ldmatrix + pre-split inputs + cp.async pipe) ----------------
// QT=128 (4 warps), KT=64. smem words:
//   Q: [0, 8704)           rows 0..127, stride 68: [hi 32w | lo 32w | pad 4w]
//   K: 2 bufs @ 8704       each 64 x 68
//   V: 2 bufs @ 17408      each 128 x 36 (rows 0-63 hi, 64-127 lo)
#define FQT 128
#define FKT 64
#define QS_W 68
#define VS_W 36
#define KB0 8704
#define KBUF_W (64 * QS_W)      // 4352
#define VB0 (KB0 + 2 * KBUF_W)  // 17408
#define VBUF_W (128 * VS_W)     // 4608
#define F_SMEM_BYTES ((VB0 + 2 * VBUF_W) * 4)   // 106496

__global__ __launch_bounds__(128) void flash_mma(
    const __nv_bfloat16* __restrict__ Qg, const __nv_bfloat16* __restrict__ Kg,
    const __nv_bfloat16* __restrict__ Vg, uint32_t* __restrict__ Cw)
{
    extern __shared__ uint32_t smw[];
    const uint32_t smb = smem_u32(smw);
    const int tid = threadIdx.x;
    const int wid = tid >> 5, lane = tid & 31;
    const int g = lane >> 2, t4 = lane & 3;
    const int bz = blockIdx.z, hh = blockIdx.y;
    const int q0 = blockIdx.x * FQT;

    // ---- issue Q (one cp.async group) ----
    {
        const char* qg = (const char*)Qg + ((size_t)(bz * N_ + q0) * 2048 + hh * 128) * 2;
#pragma unroll
        for (int u = 0; u < 16; u++) {
            int c = tid + 128 * u;
            int row = c >> 4, p = c & 15;
            cp_async16(smb + (row * QS_W + p * 4) * 4, qg + (size_t)row * 4096 + p * 16);
        }
        cp_commit();
    }
    // ---- issue K/V tile t into buf b ----
    auto issue_kv = [&](int t) {
        const int b = t & 1;
        const char* kg = (const char*)Kg + ((size_t)(bz * N_ + t * 64) * 2048 + hh * 128) * 2;
        const char* vg = (const char*)Vg + ((size_t)(bz * N_ + t * 64) * 2048 + hh * 128) * 2;
#pragma unroll
        for (int u = 0; u < 8; u++) {
            int c = tid + 128 * u;
            int row = c >> 4, p = c & 15;
            cp_async16(smb + ((KB0 + b * KBUF_W) + row * QS_W + p * 4) * 4,
                       kg + (size_t)row * 4096 + p * 16);
        }
#pragma unroll
        for (int u = 0; u < 8; u++) {
            int c = tid + 128 * u;
            int row = c >> 4, p = c & 15;
            int part = p >> 3, k = p & 7;
            cp_async16(smb + ((VB0 + b * VBUF_W) + (part * 64 + row) * VS_W + k * 4) * 4,
                       vg + (size_t)row * 4096 + p * 16);
        }
        cp_commit();
    };

    issue_kv(0);
    asm volatile("cp.async.wait_group 1;" ::: "memory");   // Q resident
    __syncthreads();

    // ---- hoist Q-hi fragments into registers (invariant over t) ----
    const int qa_row = 32 * wid + (lane & 15);
    const int qa_cw  = 4 * (lane >> 4);
    uint32_t qh[2][4][4];
#pragma unroll
    for (int i = 0; i < 2; i++)
#pragma unroll
        for (int kc = 0; kc < 4; kc++)
            ldsm4(qh[i][kc], smb + ((qa_row + 16 * i) * QS_W + qa_cw + 8 * kc) * 4);

    float o[2][8][4], mrow[2][2], lrow[2][2];
#pragma unroll
    for (int i = 0; i < 2; i++) {
        mrow[i][0] = mrow[i][1] = -CUDART_INF_F;
        lrow[i][0] = lrow[i][1] = 0.0f;
#pragma unroll
        for (int j = 0; j < 8; j++)
#pragma unroll
            for (int q = 0; q < 4; q++) o[i][j][q] = 0.0f;
    }

    const int kb_row = (lane & 7) + 8 * (lane >> 4);
    const int kb_cw  = 4 * ((lane >> 3) & 1);
    const int tsel = lane >> 3;

    for (int t = 0; t < N_ / FKT; t++) {
        if (t + 1 < N_ / FKT) {
            issue_kv(t + 1);
            asm volatile("cp.async.wait_group 1;" ::: "memory");
        } else {
            asm volatile("cp.async.wait_group 0;" ::: "memory");
        }
        __syncthreads();
        const int koff = KB0 + (t & 1) * KBUF_W;
        const int voff = VB0 + (t & 1) * VBUF_W;

        // ---- S = Q Kt : (Qh+Ql)*Kh then Qh*Kl ----
        float s[2][8][4];
#pragma unroll
        for (int i = 0; i < 2; i++)
#pragma unroll
            for (int j = 0; j < 8; j++)
#pragma unroll
                for (int q = 0; q < 4; q++) s[i][j][q] = 0.0f;

#pragma unroll
        for (int kc = 0; kc < 4; kc++) {
            uint32_t kb[8][2];
#pragma unroll
            for (int jp = 0; jp < 4; jp++) {
                uint32_t r4[4];
                ldsm4(r4, smb + (koff + (kb_row + 16 * jp) * QS_W + kb_cw + 8 * kc) * 4);
                kb[2 * jp][0] = r4[0]; kb[2 * jp][1] = r4[1];
                kb[2 * jp + 1][0] = r4[2]; kb[2 * jp + 1][1] = r4[3];
            }
#pragma unroll
            for (int i = 0; i < 2; i++)
#pragma unroll
                for (int j = 0; j < 8; j++) mma16816(s[i][j], qh[i][kc], kb[j]);
            uint32_t ql[2][4];
#pragma unroll
            for (int i = 0; i < 2; i++)
                ldsm4(ql[i], smb + ((qa_row + 16 * i) * QS_W + 32 + qa_cw + 8 * kc) * 4);
#pragma unroll
            for (int i = 0; i < 2; i++)
#pragma unroll
                for (int j = 0; j < 8; j++) mma16816(s[i][j], ql[i], kb[j]);
        }
#pragma unroll
        for (int kc = 0; kc < 4; kc++) {
            uint32_t kb[8][2];
#pragma unroll
            for (int jp = 0; jp < 4; jp++) {
                uint32_t r4[4];
                ldsm4(r4, smb + (koff + (kb_row + 16 * jp) * QS_W + 32 + kb_cw + 8 * kc) * 4);
                kb[2 * jp][0] = r4[0]; kb[2 * jp][1] = r4[1];
                kb[2 * jp + 1][0] = r4[2]; kb[2 * jp + 1][1] = r4[3];
            }
#pragma unroll
            for (int i = 0; i < 2; i++)
#pragma unroll
                for (int j = 0; j < 8; j++) mma16816(s[i][j], qh[i][kc], kb[j]);
        }

        // ---- online softmax ----
#pragma unroll
        for (int i = 0; i < 2; i++) {
#pragma unroll
            for (int h = 0; h < 2; h++) {
                float mx = -CUDART_INF_F;
#pragma unroll
                for (int j = 0; j < 8; j++)
                    mx = fmaxf(mx, fmaxf(s[i][j][2 * h], s[i][j][2 * h + 1]));
                mx = fmaxf(mx, __shfl_xor_sync(0xFFFFFFFFu, mx, 1));
                mx = fmaxf(mx, __shfl_xor_sync(0xFFFFFFFFu, mx, 2));
                float mnew = fmaxf(mrow[i][h], mx);
                float alpha = __expf(mrow[i][h] - mnew);
                mrow[i][h] = mnew;
                float ls = 0.0f;
#pragma unroll
                for (int j = 0; j < 8; j++) {
                    float p0 = __expf(s[i][j][2 * h] - mnew);
                    float p1 = __expf(s[i][j][2 * h + 1] - mnew);
                    ls += p0 + p1;
                    s[i][j][2 * h] = p0; s[i][j][2 * h + 1] = p1;
                }
                ls += __shfl_xor_sync(0xFFFFFFFFu, ls, 1);
                ls += __shfl_xor_sync(0xFFFFFFFFu, ls, 2);
                lrow[i][h] = lrow[i][h] * alpha + ls;
#pragma unroll
                for (int j = 0; j < 8; j++) {
                    o[i][j][2 * h] *= alpha; o[i][j][2 * h + 1] *= alpha;
                }
            }
        }

        // ---- pack P hi/lo (C-frag -> A-frag remap) ----
        uint32_t ph[2][8], phB[2][8], pl[2][8], plB[2][8];
#pragma unroll
        for (int i = 0; i < 2; i++)
#pragma unroll
            for (int j = 0; j < 8; j++) {
                pack_hl(s[i][j][0], s[i][j][1], ph[i][j], pl[i][j]);
                pack_hl(s[i][j][2], s[i][j][3], phB[i][j], plB[i][j]);
            }

        // ---- O += P V : (Ph+Pl)*Vh then Ph*Vl ----
#pragma unroll
        for (int kc = 0; kc < 4; kc++) {
            uint32_t vb[8][2];
#pragma unroll
            for (int jj = 0; jj < 8; jj += 2) {
                uint32_t r4[4];
                int row = 16 * kc + 8 * (tsel & 1) + (lane & 7);
                ldsm4t(r4, smb + (voff + row * VS_W) * 4 + 16 * (jj + (tsel >> 1)));
                vb[jj][0] = r4[0]; vb[jj][1] = r4[1];
                vb[jj + 1][0] = r4[2]; vb[jj + 1][1] = r4[3];
            }
#pragma unroll
            for (int i = 0; i < 2; i++) {
                uint32_t pa[4] = { ph[i][2 * kc], phB[i][2 * kc],
                                   ph[i][2 * kc + 1], phB[i][2 * kc + 1] };
#pragma unroll
                for (int j = 0; j < 8; j++) mma16816(o[i][j], pa, vb[j]);
            }
#pragma unroll
            for (int i = 0; i < 2; i++) {
                uint32_t pa[4] = { pl[i][2 * kc], plB[i][2 * kc],
                                   pl[i][2 * kc + 1], plB[i][2 * kc + 1] };
#pragma unroll
                for (int j = 0; j < 8; j++) mma16816(o[i][j], pa, vb[j]);
            }
        }
#pragma unroll
        for (int kc = 0; kc < 4; kc++) {
            uint32_t vb[8][2];
#pragma unroll
            for (int jj = 0; jj < 8; jj += 2) {
                uint32_t r4[4];
                int row = 64 + 16 * kc + 8 * (tsel & 1) + (lane & 7);
                ldsm4t(r4, smb + (voff + row * VS_W) * 4 + 16 * (jj + (tsel >> 1)));
                vb[jj][0] = r4[0]; vb[jj][1] = r4[1];
                vb[jj + 1][0] = r4[2]; vb[jj + 1][1] = r4[3];
            }
#pragma unroll
            for (int i = 0; i < 2; i++) {
                uint32_t pa[4] = { ph[i][2 * kc], phB[i][2 * kc],
                                   ph[i][2 * kc + 1], phB[i][2 * kc + 1] };
#pragma unroll
                for (int j = 0; j < 8; j++) mma16816(o[i][j], pa, vb[j]);
            }
        }
        __syncthreads();   // all warps done with buf t before it is refilled
    }

    // ---- epilogue: write split context directly into [hi|lo|hi] (1536 words/row) ----
#pragma unroll
    for (int i = 0; i < 2; i++) {
        float inv0 = 1.0f / (lrow[i][0] * 32.0f);
        float inv1 = 1.0f / (lrow[i][1] * 32.0f);
        int row = bz * N_ + q0 + 32 * wid + 16 * i + g;
#pragma unroll
        for (int j = 0; j < 8; j++) {
            int cw = (hh * 64 + 8 * j + 2 * t4) >> 1;
            uint32_t hi, lo;
            int base = row * 1536;
            pack_hl(o[i][j][0] * inv0, o[i][j][1] * inv0, hi, lo);
            Cw[base + cw] = hi; Cw[base + 512 + cw] = lo; Cw[base + 1024 + cw] = hi;
            base = (row + 8) * 1536;
            pack_hl(o[i][j][2] * inv1, o[i][j][3] * inv1, hi, lo);
            Cw[base + cw] = hi; Cw[base + 512 + cw] = lo; Cw[base + 1024 + cw] = hi;
        }
    }
}

// ---------------- launcher ----------------
extern "C" void kernel_launch(void* const* d_in, const int* in_sizes, int n_in,
                              void* d_out, int out_size)
{
    const float* x  = (const float*)d_in[0];
    const float* Wq = (const float*)d_in[1];
    const float* bq = (const float*)d_in[2];
    const float* Wk = (const float*)d_in[3];
    const float* bk = (const float*)d_in[4];
    const float* Wv = (const float*)d_in[5];
    const float* bv = (const float*)d_in[6];
    const float* Wo = (const float*)d_in[7];
    const float* bo = (const float*)d_in[8];
    float* out = (float*)d_out;

    cudaFuncSetAttribute(gemm_mma_t<1>, cudaFuncAttributeMaxDynamicSharedMemorySize, G_SMEM_BYTES);
    cudaFuncSetAttribute(gemm_mma_t<0>, cudaFuncAttributeMaxDynamicSharedMemorySize, G_SMEM_BYTES);
    cudaFuncSetAttribute(flash_mma, cudaFuncAttributeMaxDynamicSharedMemorySize, F_SMEM_BYTES);

    __nv_bfloat16 *Qs, *Ks, *Vs, *xe, *ce, *wqe, *wke, *wve, *woe;
    cudaGetSymbolAddress((void**)&Qs, g_Qs);
    cudaGetSymbolAddress((void**)&Ks, g_Ks);
    cudaGetSymbolAddress((void**)&Vs, g_Vs);
    cudaGetSymbolAddress((void**)&xe, g_xext);
    cudaGetSymbolAddress((void**)&ce, g_cext);
    cudaGetSymbolAddress((void**)&wqe, g_wqext);
    cudaGetSymbolAddress((void**)&wke, g_wkext);
    cudaGetSymbolAddress((void**)&wve, g_wvext);
    cudaGetSymbolAddress((void**)&woe, g_woext);

    cvt_x<<<M_, 256>>>(x, xe);
    dim3 wgrid(E_, 4);
    cvt_w4<<<wgrid, 256>>>(Wq, Wk, Wv, Wo, wqe, wke, wve, woe);

    dim3 ggrid3(E_ / 128, M_ / 128, 3);   // (8, 32, 3)
    gemm_mma_t<1><<<ggrid3, 256, G_SMEM_BYTES>>>(
        xe, wqe, wke, wve, bq, bk, bv, nullptr, Qs, Ks, Vs);

    dim3 fgrid(N_ / FQT, H_, B_);         // (16, 16, 2)
    flash_mma<<<fgrid, 128, F_SMEM_BYTES>>>(Qs, Ks, Vs, (uint32_t*)ce);

    dim3 ggrid1(E_ / 128, M_ / 128, 1);
    gemm_mma_t<0><<<ggrid1, 256, G_SMEM_BYTES>>>(
        ce, woe, woe, woe, bo, bo, bo, out, nullptr, nullptr, nullptr);
}

// round 6
// speedup vs baseline: 3.3803x; 1.0323x over previous
#include <cuda_runtime.h>
#include <cuda_bf16.h>
#include <math_constants.h>
#include <cstdint>

#define B_  2
#define N_  2048
#define E_  1024
#define H_  16
#define D_  64
#define M_  (B_ * N_)
#define K3_ 3072

// ---------------- scratch ----------------
__device__ __nv_bfloat16 g_Qs[M_ * 2048];     // [row][head][64hi|64lo]
__device__ __nv_bfloat16 g_Ks[M_ * 2048];
__device__ __nv_bfloat16 g_Vs[M_ * 2048];
__device__ __nv_bfloat16 g_xext[M_ * K3_];    // [hi|lo|hi]
__device__ __nv_bfloat16 g_cext[M_ * K3_];    // [hi|lo|hi], written by flash
__device__ __nv_bfloat16 g_wqext[E_ * K3_];   // [hi|hi|lo]
__device__ __nv_bfloat16 g_wkext[E_ * K3_];
__device__ __nv_bfloat16 g_wvext[E_ * K3_];
__device__ __nv_bfloat16 g_woext[E_ * K3_];

// ---------------- helpers ----------------
__device__ __forceinline__ uint32_t smem_u32(const void* p) {
    uint32_t a;
    asm("{ .reg .u64 t; cvta.to.shared.u64 t, %1; cvt.u32.u64 %0, t; }" : "=r"(a) : "l"(p));
    return a;
}
__device__ __forceinline__ void mma16816(float* c, const uint32_t* a, const uint32_t* b) {
    asm volatile(
        "mma.sync.aligned.m16n8k16.row.col.f32.bf16.bf16.f32 "
        "{%0,%1,%2,%3}, {%4,%5,%6,%7}, {%8,%9}, {%0,%1,%2,%3};"
        : "+f"(c[0]), "+f"(c[1]), "+f"(c[2]), "+f"(c[3])
        : "r"(a[0]), "r"(a[1]), "r"(a[2]), "r"(a[3]), "r"(b[0]), "r"(b[1]));
}
__device__ __forceinline__ void ldsm4(uint32_t* r, uint32_t addr) {
    asm volatile("ldmatrix.sync.aligned.m8n8.x4.shared.b16 {%0,%1,%2,%3}, [%4];"
        : "=r"(r[0]), "=r"(r[1]), "=r"(r[2]), "=r"(r[3]) : "r"(addr));
}
__device__ __forceinline__ void ldsm4t(uint32_t* r, uint32_t addr) {
    asm volatile("ldmatrix.sync.aligned.m8n8.x4.trans.shared.b16 {%0,%1,%2,%3}, [%4];"
        : "=r"(r[0]), "=r"(r[1]), "=r"(r[2]), "=r"(r[3]) : "r"(addr));
}
__device__ __forceinline__ void cp_async16(uint32_t s, const void* g) {
    asm volatile("cp.async.cg.shared.global [%0], [%1], 16;" :: "r"(s), "l"(g) : "memory");
}
__device__ __forceinline__ void cp_commit() {
    asm volatile("cp.async.commit_group;" ::: "memory");
}
__device__ __forceinline__ void pack_hl(float x, float y, uint32_t& hi, uint32_t& lo) {
    __nv_bfloat162 h2 = __floats2bfloat162_rn(x, y);
    float rx = x - __bfloat162float(h2.x);
    float ry = y - __bfloat162float(h2.y);
    __nv_bfloat162 l2 = __floats2bfloat162_rn(rx, ry);
    hi = *reinterpret_cast<uint32_t*>(&h2);
    lo = *reinterpret_cast<uint32_t*>(&l2);
}

// ---------------- x conversion: [hi|lo|hi] ----------------
__global__ __launch_bounds__(256) void cvt_x(
    const float* __restrict__ in, __nv_bfloat16* __restrict__ out)
{
    int idx = blockIdx.x * 256 + threadIdx.x;
    int r = idx >> 8;
    int c = (idx & 255) << 2;
    float4 v = *reinterpret_cast<const float4*>(in + (size_t)r * E_ + c);
    uint32_t h0, l0, h1, l1;
    pack_hl(v.x, v.y, h0, l0);
    pack_hl(v.z, v.w, h1, l1);
    uint32_t* o = reinterpret_cast<uint32_t*>(out + (size_t)r * K3_);
    int cw = c >> 1;
    o[cw] = h0; o[cw + 1] = h1;
    o[512 + cw] = l0; o[512 + cw + 1] = l1;
    o[1024 + cw] = h0; o[1024 + cw + 1] = h1;
}

// ---------------- weight conversion (4 fused): [hi|hi|lo] ----------------
__global__ __launch_bounds__(256) void cvt_w4(
    const float* __restrict__ W0, const float* __restrict__ W1,
    const float* __restrict__ W2, const float* __restrict__ W3,
    __nv_bfloat16* __restrict__ O0, __nv_bfloat16* __restrict__ O1,
    __nv_bfloat16* __restrict__ O2, __nv_bfloat16* __restrict__ O3)
{
    int sel = blockIdx.y;
    const float* in = sel == 0 ? W0 : sel == 1 ? W1 : sel == 2 ? W2 : W3;
    __nv_bfloat16* out = sel == 0 ? O0 : sel == 1 ? O1 : sel == 2 ? O2 : O3;
    int idx = blockIdx.x * 256 + threadIdx.x;
    int r = idx >> 8;
    int c = (idx & 255) << 2;
    float4 v = *reinterpret_cast<const float4*>(in + (size_t)r * E_ + c);
    uint32_t h0, l0, h1, l1;
    pack_hl(v.x, v.y, h0, l0);
    pack_hl(v.z, v.w, h1, l1);
    uint32_t* o = reinterpret_cast<uint32_t*>(out + (size_t)r * K3_);
    int cw = c >> 1;
    o[cw] = h0; o[cw + 1] = h1;
    o[512 + cw] = h0;  o[512 + cw + 1] = h1;
    o[1024 + cw] = l0; o[1024 + cw + 1] = l1;
}

// ---------------- HMMA NT GEMM (ldmatrix), 2 CTAs/SM ----------------
#define GS_W 20
#define G_STAGE_W (256 * GS_W)
#define G_SMEM_BYTES (3 * G_STAGE_W * 4)

template<int SPLIT>
__global__ __launch_bounds__(256, 2) void gemm_mma_t(
    const __nv_bfloat16* __restrict__ A,
    const __nv_bfloat16* __restrict__ W0, const __nv_bfloat16* __restrict__ W1,
    const __nv_bfloat16* __restrict__ W2,
    const float* __restrict__ b0, const float* __restrict__ b1, const float* __restrict__ b2,
    float* __restrict__ Cf,
    __nv_bfloat16* __restrict__ S0, __nv_bfloat16* __restrict__ S1,
    __nv_bfloat16* __restrict__ S2)
{
    extern __shared__ uint32_t smw[];
    const int z = blockIdx.z;
    const __nv_bfloat16* W = (z == 0) ? W0 : (z == 1) ? W1 : W2;
    const float* bias = (z == 0) ? b0 : (z == 1) ? b1 : b2;
    __nv_bfloat16* Sp = (z == 0) ? S0 : (z == 1) ? S1 : S2;

    const int tid = threadIdx.x;
    const int wid = tid >> 5, lane = tid & 31;
    const int g = lane >> 2, t4 = lane & 3;
    const int wm = wid & 3, wn = wid >> 2;
    const int m0 = blockIdx.y * 128;
    const int n0 = blockIdx.x * 128;
    const int NT = K3_ / 32;   // 96
    const uint32_t smb = smem_u32(smw);

    auto issue = [&](int kt) {
        const int sb = (kt % 3) * G_STAGE_W;
#pragma unroll
        for (int u = 0; u < 2; u++) {
            int c = tid + 256 * u;
            int row = c >> 2, k4 = c & 3;
            uint32_t sa = smb + (sb + row * GS_W + k4 * 4) * 4;
            cp_async16(sa, A + (size_t)(m0 + row) * K3_ + kt * 32 + k4 * 8);
            cp_async16(sa + 128 * GS_W * 4, W + (size_t)(n0 + row) * K3_ + kt * 32 + k4 * 8);
        }
        cp_commit();
    };

    float acc[2][8][4];
#pragma unroll
    for (int i = 0; i < 2; i++)
#pragma unroll
        for (int j = 0; j < 8; j++)
#pragma unroll
            for (int q = 0; q < 4; q++) acc[i][j][q] = 0.0f;

    issue(0);
    issue(1);

    const int a_row = 32 * wm + (lane & 15);
    const int a_cw  = 4 * (lane >> 4);
    const int b_row = 64 * wn + (lane & 7) + 8 * (lane >> 4);
    const int b_cw  = 4 * ((lane >> 3) & 1);

    for (int kt = 0; kt < NT; kt++) {
        if (kt < NT - 1) asm volatile("cp.async.wait_group 1;" ::: "memory");
        else             asm volatile("cp.async.wait_group 0;" ::: "memory");
        __syncthreads();
        if (kt + 2 < NT) issue(kt + 2);

        const int sb = (kt % 3) * G_STAGE_W;
        const int bb = sb + 128 * GS_W;
#pragma unroll
        for (int kk = 0; kk < 2; kk++) {
            uint32_t a[2][4], b[8][2];
#pragma unroll
            for (int i = 0; i < 2; i++)
                ldsm4(a[i], smb + (sb + (a_row + 16 * i) * GS_W + a_cw + 8 * kk) * 4);
#pragma unroll
            for (int jp = 0; jp < 4; jp++) {
                uint32_t r4[4];
                ldsm4(r4, smb + (bb + (b_row + 16 * jp) * GS_W + b_cw + 8 * kk) * 4);
                b[2 * jp][0] = r4[0]; b[2 * jp][1] = r4[1];
                b[2 * jp + 1][0] = r4[2]; b[2 * jp + 1][1] = r4[3];
            }
#pragma unroll
            for (int i = 0; i < 2; i++)
#pragma unroll
                for (int j = 0; j < 8; j++) mma16816(acc[i][j], a[i], b[j]);
        }
    }

    if (SPLIT) {
        const int head = (n0 + 64 * wn) >> 6;
        uint32_t* outw = reinterpret_cast<uint32_t*>(Sp);
#pragma unroll
        for (int i = 0; i < 2; i++) {
            int row = m0 + 32 * wm + 16 * i + g;
#pragma unroll
            for (int j = 0; j < 8; j++) {
                int d = 8 * j + 2 * t4;
                float2 bb2 = *reinterpret_cast<const float2*>(bias + n0 + 64 * wn + d);
                uint32_t hi, lo;
                int w0 = row * 1024 + head * 64 + (d >> 1);
                pack_hl(acc[i][j][0] + bb2.x, acc[i][j][1] + bb2.y, hi, lo);
                outw[w0] = hi; outw[w0 + 32] = lo;
                w0 += 8 * 1024;
                pack_hl(acc[i][j][2] + bb2.x, acc[i][j][3] + bb2.y, hi, lo);
                outw[w0] = hi; outw[w0 + 32] = lo;
            }
        }
    } else {
#pragma unroll
        for (int i = 0; i < 2; i++) {
            int row = m0 + 32 * wm + 16 * i + g;
#pragma unroll
            for (int j = 0; j < 8; j++) {
                int col = n0 + 64 * wn + 8 * j + 2 * t4;
                float2 bb2 = *reinterpret_cast<const float2*>(bias + col);
                float2 v0 = { acc[i][j][0] + bb2.x, acc[i][j][1] + bb2.y };
                float2 v1 = { acc[i][j][2] + bb2.x, acc[i][j][3] + bb2.y };
                *reinterpret_cast<float2*>(Cf + (size_t)row * E_ + col) = v0;
                *reinterpret_cast<float2*>(Cf + (size_t)(row + 8) * E_ + col) = v1;
            }
        }
    }
}

// ---------------- Flash attention: 256 threads, 8 warps x m16, 2 CTAs/SM ----------------
// QT=128, KT=64. smem words:
//   Q: [0, 8704)  rows 0..127, stride 68: [hi 32w | lo 32w | pad 4w]
//   K: 2 bufs @ 8704, each 64 x 68
//   V: 2 bufs @ 17408, each 128 x 36 (rows 0-63 hi, 64-127 lo)
#define FQT 128
#define FKT 64
#define QS_W 68
#define VS_W 36
#define KB0 8704
#define KBUF_W (64 * QS_W)
#define VB0 (KB0 + 2 * KBUF_W)
#define VBUF_W (128 * VS_W)
#define F_SMEM_BYTES ((VB0 + 2 * VBUF_W) * 4)   // 106496

__global__ __launch_bounds__(256, 2) void flash_mma(
    const __nv_bfloat16* __restrict__ Qg, const __nv_bfloat16* __restrict__ Kg,
    const __nv_bfloat16* __restrict__ Vg, uint32_t* __restrict__ Cw)
{
    extern __shared__ uint32_t smw[];
    const uint32_t smb = smem_u32(smw);
    const int tid = threadIdx.x;
    const int wid = tid >> 5, lane = tid & 31;
    const int g = lane >> 2, t4 = lane & 3;
    const int bz = blockIdx.z, hh = blockIdx.y;
    const int q0 = blockIdx.x * FQT;

    // ---- issue Q (one cp.async group): 2048 16B-chunks / 256 threads ----
    {
        const char* qg = (const char*)Qg + ((size_t)(bz * N_ + q0) * 2048 + hh * 128) * 2;
#pragma unroll
        for (int u = 0; u < 8; u++) {
            int c = tid + 256 * u;
            int row = c >> 4, p = c & 15;
            cp_async16(smb + (row * QS_W + p * 4) * 4, qg + (size_t)row * 4096 + p * 16);
        }
        cp_commit();
    }
    auto issue_kv = [&](int t) {
        const int b = t & 1;
        const char* kg = (const char*)Kg + ((size_t)(bz * N_ + t * 64) * 2048 + hh * 128) * 2;
        const char* vg = (const char*)Vg + ((size_t)(bz * N_ + t * 64) * 2048 + hh * 128) * 2;
#pragma unroll
        for (int u = 0; u < 4; u++) {
            int c = tid + 256 * u;
            int row = c >> 4, p = c & 15;
            cp_async16(smb + ((KB0 + b * KBUF_W) + row * QS_W + p * 4) * 4,
                       kg + (size_t)row * 4096 + p * 16);
        }
#pragma unroll
        for (int u = 0; u < 4; u++) {
            int c = tid + 256 * u;
            int row = c >> 4, p = c & 15;
            int part = p >> 3, k = p & 7;
            cp_async16(smb + ((VB0 + b * VBUF_W) + (part * 64 + row) * VS_W + k * 4) * 4,
                       vg + (size_t)row * 4096 + p * 16);
        }
        cp_commit();
    };

    issue_kv(0);
    asm volatile("cp.async.wait_group 1;" ::: "memory");   // Q resident
    __syncthreads();

    // ---- hoist Q-hi fragments (m16: one ldsm4 per k-chunk) ----
    const int qa_row = 16 * wid + (lane & 15);
    const int qa_cw  = 4 * (lane >> 4);
    uint32_t qh[4][4];
#pragma unroll
    for (int kc = 0; kc < 4; kc++)
        ldsm4(qh[kc], smb + (qa_row * QS_W + qa_cw + 8 * kc) * 4);

    float o[8][4], mrow[2], lrow[2];
    mrow[0] = mrow[1] = -CUDART_INF_F;
    lrow[0] = lrow[1] = 0.0f;
#pragma unroll
    for (int j = 0; j < 8; j++)
#pragma unroll
        for (int q = 0; q < 4; q++) o[j][q] = 0.0f;

    const int kb_row = (lane & 7) + 8 * (lane >> 4);
    const int kb_cw  = 4 * ((lane >> 3) & 1);
    const int tsel = lane >> 3;

    for (int t = 0; t < N_ / FKT; t++) {
        if (t + 1 < N_ / FKT) {
            issue_kv(t + 1);
            asm volatile("cp.async.wait_group 1;" ::: "memory");
        } else {
            asm volatile("cp.async.wait_group 0;" ::: "memory");
        }
        __syncthreads();
        const int koff = KB0 + (t & 1) * KBUF_W;
        const int voff = VB0 + (t & 1) * VBUF_W;

        // ---- S = Q Kt : (Qh+Ql)*Kh then Qh*Kl ----
        float s[8][4];
#pragma unroll
        for (int j = 0; j < 8; j++)
#pragma unroll
            for (int q = 0; q < 4; q++) s[j][q] = 0.0f;

#pragma unroll
        for (int kc = 0; kc < 4; kc++) {
            uint32_t kb[8][2];
#pragma unroll
            for (int jp = 0; jp < 4; jp++) {
                uint32_t r4[4];
                ldsm4(r4, smb + (koff + (kb_row + 16 * jp) * QS_W + kb_cw + 8 * kc) * 4);
                kb[2 * jp][0] = r4[0]; kb[2 * jp][1] = r4[1];
                kb[2 * jp + 1][0] = r4[2]; kb[2 * jp + 1][1] = r4[3];
            }
#pragma unroll
            for (int j = 0; j < 8; j++) mma16816(s[j], qh[kc], kb[j]);
            uint32_t ql[4];
            ldsm4(ql, smb + (qa_row * QS_W + 32 + qa_cw + 8 * kc) * 4);
#pragma unroll
            for (int j = 0; j < 8; j++) mma16816(s[j], ql, kb[j]);
        }
#pragma unroll
        for (int kc = 0; kc < 4; kc++) {
            uint32_t kb[8][2];
#pragma unroll
            for (int jp = 0; jp < 4; jp++) {
                uint32_t r4[4];
                ldsm4(r4, smb + (koff + (kb_row + 16 * jp) * QS_W + 32 + kb_cw + 8 * kc) * 4);
                kb[2 * jp][0] = r4[0]; kb[2 * jp][1] = r4[1];
                kb[2 * jp + 1][0] = r4[2]; kb[2 * jp + 1][1] = r4[3];
            }
#pragma unroll
            for (int j = 0; j < 8; j++) mma16816(s[j], qh[kc], kb[j]);
        }

        // ---- online softmax (h=0: row g, h=1: row g+8) ----
#pragma unroll
        for (int h = 0; h < 2; h++) {
            float mx = -CUDART_INF_F;
#pragma unroll
            for (int j = 0; j < 8; j++)
                mx = fmaxf(mx, fmaxf(s[j][2 * h], s[j][2 * h + 1]));
            mx = fmaxf(mx, __shfl_xor_sync(0xFFFFFFFFu, mx, 1));
            mx = fmaxf(mx, __shfl_xor_sync(0xFFFFFFFFu, mx, 2));
            float mnew = fmaxf(mrow[h], mx);
            float alpha = __expf(mrow[h] - mnew);
            mrow[h] = mnew;
            float ls = 0.0f;
#pragma unroll
            for (int j = 0; j < 8; j++) {
                float p0 = __expf(s[j][2 * h] - mnew);
                float p1 = __expf(s[j][2 * h + 1] - mnew);
                ls += p0 + p1;
                s[j][2 * h] = p0; s[j][2 * h + 1] = p1;
            }
            ls += __shfl_xor_sync(0xFFFFFFFFu, ls, 1);
            ls += __shfl_xor_sync(0xFFFFFFFFu, ls, 2);
            lrow[h] = lrow[h] * alpha + ls;
#pragma unroll
            for (int j = 0; j < 8; j++) {
                o[j][2 * h] *= alpha; o[j][2 * h + 1] *= alpha;
            }
        }

        // ---- pack P hi/lo (C-frag -> A-frag remap) ----
        uint32_t ph[8], phB[8], pl[8], plB[8];
#pragma unroll
        for (int j = 0; j < 8; j++) {
            pack_hl(s[j][0], s[j][1], ph[j], pl[j]);
            pack_hl(s[j][2], s[j][3], phB[j], plB[j]);
        }

        // ---- O += P V : (Ph+Pl)*Vh then Ph*Vl ----
#pragma unroll
        for (int kc = 0; kc < 4; kc++) {
            uint32_t vb[8][2];
#pragma unroll
            for (int jj = 0; jj < 8; jj += 2) {
                uint32_t r4[4];
                int row = 16 * kc + 8 * (tsel & 1) + (lane & 7);
                ldsm4t(r4, smb + (voff + row * VS_W) * 4 + 16 * (jj + (tsel >> 1)));
                vb[jj][0] = r4[0]; vb[jj][1] = r4[1];
                vb[jj + 1][0] = r4[2]; vb[jj + 1][1] = r4[3];
            }
            {
                uint32_t pa[4] = { ph[2 * kc], phB[2 * kc], ph[2 * kc + 1], phB[2 * kc + 1] };
#pragma unroll
                for (int j = 0; j < 8; j++) mma16816(o[j], pa, vb[j]);
            }
            {
                uint32_t pa[4] = { pl[2 * kc], plB[2 * kc], pl[2 * kc + 1], plB[2 * kc + 1] };
#pragma unroll
                for (int j = 0; j < 8; j++) mma16816(o[j], pa, vb[j]);
            }
        }
#pragma unroll
        for (int kc = 0; kc < 4; kc++) {
            uint32_t vb[8][2];
#pragma unroll
            for (int jj = 0; jj < 8; jj += 2) {
                uint32_t r4[4];
                int row = 64 + 16 * kc + 8 * (tsel & 1) + (lane & 7);
                ldsm4t(r4, smb + (voff + row * VS_W) * 4 + 16 * (jj + (tsel >> 1)));
                vb[jj][0] = r4[0]; vb[jj][1] = r4[1];
                vb[jj + 1][0] = r4[2]; vb[jj + 1][1] = r4[3];
            }
            uint32_t pa[4] = { ph[2 * kc], phB[2 * kc], ph[2 * kc + 1], phB[2 * kc + 1] };
#pragma unroll
            for (int j = 0; j < 8; j++) mma16816(o[j], pa, vb[j]);
        }
        __syncthreads();
    }

    // ---- epilogue: write split context into [hi|lo|hi] (1536 words/row) ----
    float inv0 = 1.0f / (lrow[0] * 32.0f);
    float inv1 = 1.0f / (lrow[1] * 32.0f);
    int row = bz * N_ + q0 + 16 * wid + g;
#pragma unroll
    for (int j = 0; j < 8; j++) {
        int cw = (hh * 64 + 8 * j + 2 * t4) >> 1;
        uint32_t hi, lo;
        int base = row * 1536;
        pack_hl(o[j][0] * inv0, o[j][1] * inv0, hi, lo);
        Cw[base + cw] = hi; Cw[base + 512 + cw] = lo; Cw[base + 1024 + cw] = hi;
        base = (row + 8) * 1536;
        pack_hl(o[j][2] * inv1, o[j][3] * inv1, hi, lo);
        Cw[base + cw] = hi; Cw[base + 512 + cw] = lo; Cw[base + 1024 + cw] = hi;
    }
}

// ---------------- launcher ----------------
extern "C" void kernel_launch(void* const* d_in, const int* in_sizes, int n_in,
                              void* d_out, int out_size)
{
    const float* x  = (const float*)d_in[0];
    const float* Wq = (const float*)d_in[1];
    const float* bq = (const float*)d_in[2];
    const float* Wk = (const float*)d_in[3];
    const float* bk = (const float*)d_in[4];
    const float* Wv = (const float*)d_in[5];
    const float* bv = (const float*)d_in[6];
    const float* Wo = (const float*)d_in[7];
    const float* bo = (const float*)d_in[8];
    float* out = (float*)d_out;

    cudaFuncSetAttribute(gemm_mma_t<1>, cudaFuncAttributeMaxDynamicSharedMemorySize, G_SMEM_BYTES);
    cudaFuncSetAttribute(gemm_mma_t<0>, cudaFuncAttributeMaxDynamicSharedMemorySize, G_SMEM_BYTES);
    cudaFuncSetAttribute(flash_mma, cudaFuncAttributeMaxDynamicSharedMemorySize, F_SMEM_BYTES);

    __nv_bfloat16 *Qs, *Ks, *Vs, *xe, *ce, *wqe, *wke, *wve, *woe;
    cudaGetSymbolAddress((void**)&Qs, g_Qs);
    cudaGetSymbolAddress((void**)&Ks, g_Ks);
    cudaGetSymbolAddress((void**)&Vs, g_Vs);
    cudaGetSymbolAddress((void**)&xe, g_xext);
    cudaGetSymbolAddress((void**)&ce, g_cext);
    cudaGetSymbolAddress((void**)&wqe, g_wqext);
    cudaGetSymbolAddress((void**)&wke, g_wkext);
    cudaGetSymbolAddress((void**)&wve, g_wvext);
    cudaGetSymbolAddress((void**)&woe, g_woext);

    cvt_x<<<M_, 256>>>(x, xe);
    dim3 wgrid(E_, 4);
    cvt_w4<<<wgrid, 256>>>(Wq, Wk, Wv, Wo, wqe, wke, wve, woe);

    dim3 ggrid3(E_ / 128, M_ / 128, 3);
    gemm_mma_t<1><<<ggrid3, 256, G_SMEM_BYTES>>>(
        xe, wqe, wke, wve, bq, bk, bv, nullptr, Qs, Ks, Vs);

    dim3 fgrid(N_ / FQT, H_, B_);
    flash_mma<<<fgrid, 256, F_SMEM_BYTES>>>(Qs, Ks, Vs, (uint32_t*)ce);

    dim3 ggrid1(E_ / 128, M_ / 128, 1);
    gemm_mma_t<0><<<ggrid1, 256, G_SMEM_BYTES>>>(
        ce, woe, woe, woe, bo, bo, bo, out, nullptr, nullptr, nullptr);
}

// round 7
// speedup vs baseline: 3.4752x; 1.0281x over previous
#include <cuda_runtime.h>
#include <cuda_bf16.h>
#include <math_constants.h>
#include <cstdint>

#define B_  2
#define N_  2048
#define E_  1024
#define H_  16
#define D_  64
#define M_  (B_ * N_)
#define K3_ 3072

// ---------------- scratch ----------------
__device__ __nv_bfloat16 g_Qs[M_ * 2048];     // [row][head][64hi|64lo]
__device__ __nv_bfloat16 g_Ks[M_ * 2048];
__device__ __nv_bfloat16 g_Vs[M_ * 2048];
__device__ __nv_bfloat16 g_xext[M_ * K3_];    // [hi|lo|hi]
__device__ __nv_bfloat16 g_cext[M_ * K3_];    // [hi|lo|hi], written by flash
__device__ __nv_bfloat16 g_wqext[E_ * K3_];   // [hi|hi|lo]
__device__ __nv_bfloat16 g_wkext[E_ * K3_];
__device__ __nv_bfloat16 g_wvext[E_ * K3_];
__device__ __nv_bfloat16 g_woext[E_ * K3_];

// ---------------- helpers ----------------
__device__ __forceinline__ uint32_t smem_u32(const void* p) {
    uint32_t a;
    asm("{ .reg .u64 t; cvta.to.shared.u64 t, %1; cvt.u32.u64 %0, t; }" : "=r"(a) : "l"(p));
    return a;
}
__device__ __forceinline__ void mma16816(float* c, const uint32_t* a, const uint32_t* b) {
    asm volatile(
        "mma.sync.aligned.m16n8k16.row.col.f32.bf16.bf16.f32 "
        "{%0,%1,%2,%3}, {%4,%5,%6,%7}, {%8,%9}, {%0,%1,%2,%3};"
        : "+f"(c[0]), "+f"(c[1]), "+f"(c[2]), "+f"(c[3])
        : "r"(a[0]), "r"(a[1]), "r"(a[2]), "r"(a[3]), "r"(b[0]), "r"(b[1]));
}
__device__ __forceinline__ void ldsm4(uint32_t* r, uint32_t addr) {
    asm volatile("ldmatrix.sync.aligned.m8n8.x4.shared.b16 {%0,%1,%2,%3}, [%4];"
        : "=r"(r[0]), "=r"(r[1]), "=r"(r[2]), "=r"(r[3]) : "r"(addr));
}
__device__ __forceinline__ void ldsm4t(uint32_t* r, uint32_t addr) {
    asm volatile("ldmatrix.sync.aligned.m8n8.x4.trans.shared.b16 {%0,%1,%2,%3}, [%4];"
        : "=r"(r[0]), "=r"(r[1]), "=r"(r[2]), "=r"(r[3]) : "r"(addr));
}
__device__ __forceinline__ void cp_async16(uint32_t s, const void* g) {
    asm volatile("cp.async.cg.shared.global [%0], [%1], 16;" :: "r"(s), "l"(g) : "memory");
}
__device__ __forceinline__ void cp_commit() {
    asm volatile("cp.async.commit_group;" ::: "memory");
}
__device__ __forceinline__ void pack_hl(float x, float y, uint32_t& hi, uint32_t& lo) {
    __nv_bfloat162 h2 = __floats2bfloat162_rn(x, y);
    float rx = x - __bfloat162float(h2.x);
    float ry = y - __bfloat162float(h2.y);
    __nv_bfloat162 l2 = __floats2bfloat162_rn(rx, ry);
    hi = *reinterpret_cast<uint32_t*>(&h2);
    lo = *reinterpret_cast<uint32_t*>(&l2);
}

// ---------------- x conversion: [hi|lo|hi] ----------------
__global__ __launch_bounds__(256) void cvt_x(
    const float* __restrict__ in, __nv_bfloat16* __restrict__ out)
{
    int idx = blockIdx.x * 256 + threadIdx.x;
    int r = idx >> 8;
    int c = (idx & 255) << 2;
    float4 v = *reinterpret_cast<const float4*>(in + (size_t)r * E_ + c);
    uint32_t h0, l0, h1, l1;
    pack_hl(v.x, v.y, h0, l0);
    pack_hl(v.z, v.w, h1, l1);
    uint32_t* o = reinterpret_cast<uint32_t*>(out + (size_t)r * K3_);
    int cw = c >> 1;
    o[cw] = h0; o[cw + 1] = h1;
    o[512 + cw] = l0; o[512 + cw + 1] = l1;
    o[1024 + cw] = h0; o[1024 + cw + 1] = h1;
}

// ---------------- weight conversion (4 fused): [hi|hi|lo] ----------------
__global__ __launch_bounds__(256) void cvt_w4(
    const float* __restrict__ W0, const float* __restrict__ W1,
    const float* __restrict__ W2, const float* __restrict__ W3,
    __nv_bfloat16* __restrict__ O0, __nv_bfloat16* __restrict__ O1,
    __nv_bfloat16* __restrict__ O2, __nv_bfloat16* __restrict__ O3)
{
    int sel = blockIdx.y;
    const float* in = sel == 0 ? W0 : sel == 1 ? W1 : sel == 2 ? W2 : W3;
    __nv_bfloat16* out = sel == 0 ? O0 : sel == 1 ? O1 : sel == 2 ? O2 : O3;
    int idx = blockIdx.x * 256 + threadIdx.x;
    int r = idx >> 8;
    int c = (idx & 255) << 2;
    float4 v = *reinterpret_cast<const float4*>(in + (size_t)r * E_ + c);
    uint32_t h0, l0, h1, l1;
    pack_hl(v.x, v.y, h0, l0);
    pack_hl(v.z, v.w, h1, l1);
    uint32_t* o = reinterpret_cast<uint32_t*>(out + (size_t)r * K3_);
    int cw = c >> 1;
    o[cw] = h0; o[cw + 1] = h1;
    o[512 + cw] = h0;  o[512 + cw + 1] = h1;
    o[1024 + cw] = l0; o[1024 + cw + 1] = l1;
}

// ---------------- HMMA NT GEMM (ldmatrix), 4-stage pipeline, 2 CTAs/SM ----------------
#define GS_W 20
#define G_STAGE_W (256 * GS_W)
#define G_SMEM_BYTES (4 * G_STAGE_W * 4)   // 81920

template<int SPLIT>
__global__ __launch_bounds__(256, 2) void gemm_mma_t(
    const __nv_bfloat16* __restrict__ A,
    const __nv_bfloat16* __restrict__ W0, const __nv_bfloat16* __restrict__ W1,
    const __nv_bfloat16* __restrict__ W2,
    const float* __restrict__ b0, const float* __restrict__ b1, const float* __restrict__ b2,
    float* __restrict__ Cf,
    __nv_bfloat16* __restrict__ S0, __nv_bfloat16* __restrict__ S1,
    __nv_bfloat16* __restrict__ S2)
{
    extern __shared__ uint32_t smw[];
    const int z = blockIdx.z;
    const __nv_bfloat16* W = (z == 0) ? W0 : (z == 1) ? W1 : W2;
    const float* bias = (z == 0) ? b0 : (z == 1) ? b1 : b2;
    __nv_bfloat16* Sp = (z == 0) ? S0 : (z == 1) ? S1 : S2;

    const int tid = threadIdx.x;
    const int wid = tid >> 5, lane = tid & 31;
    const int g = lane >> 2, t4 = lane & 3;
    const int wm = wid & 3, wn = wid >> 2;
    const int m0 = blockIdx.y * 128;
    const int n0 = blockIdx.x * 128;
    const int NT = K3_ / 32;   // 96
    const uint32_t smb = smem_u32(smw);

    auto issue = [&](int kt) {
        const int sb = (kt & 3) * G_STAGE_W;
#pragma unroll
        for (int u = 0; u < 2; u++) {
            int c = tid + 256 * u;
            int row = c >> 2, k4 = c & 3;
            uint32_t sa = smb + (sb + row * GS_W + k4 * 4) * 4;
            cp_async16(sa, A + (size_t)(m0 + row) * K3_ + kt * 32 + k4 * 8);
            cp_async16(sa + 128 * GS_W * 4, W + (size_t)(n0 + row) * K3_ + kt * 32 + k4 * 8);
        }
        cp_commit();
    };

    float acc[2][8][4];
#pragma unroll
    for (int i = 0; i < 2; i++)
#pragma unroll
        for (int j = 0; j < 8; j++)
#pragma unroll
            for (int q = 0; q < 4; q++) acc[i][j][q] = 0.0f;

    issue(0);
    issue(1);
    issue(2);

    const int a_row = 32 * wm + (lane & 15);
    const int a_cw  = 4 * (lane >> 4);
    const int b_row = 64 * wn + (lane & 7) + 8 * (lane >> 4);
    const int b_cw  = 4 * ((lane >> 3) & 1);

    for (int kt = 0; kt < NT; kt++) {
        if (kt < NT - 2)       asm volatile("cp.async.wait_group 2;" ::: "memory");
        else if (kt == NT - 2) asm volatile("cp.async.wait_group 1;" ::: "memory");
        else                   asm volatile("cp.async.wait_group 0;" ::: "memory");
        __syncthreads();
        if (kt + 3 < NT) issue(kt + 3);

        const int sb = (kt & 3) * G_STAGE_W;
        const int bb = sb + 128 * GS_W;
#pragma unroll
        for (int kk = 0; kk < 2; kk++) {
            uint32_t a[2][4], b[8][2];
#pragma unroll
            for (int i = 0; i < 2; i++)
                ldsm4(a[i], smb + (sb + (a_row + 16 * i) * GS_W + a_cw + 8 * kk) * 4);
#pragma unroll
            for (int jp = 0; jp < 4; jp++) {
                uint32_t r4[4];
                ldsm4(r4, smb + (bb + (b_row + 16 * jp) * GS_W + b_cw + 8 * kk) * 4);
                b[2 * jp][0] = r4[0]; b[2 * jp][1] = r4[1];
                b[2 * jp + 1][0] = r4[2]; b[2 * jp + 1][1] = r4[3];
            }
#pragma unroll
            for (int i = 0; i < 2; i++)
#pragma unroll
                for (int j = 0; j < 8; j++) mma16816(acc[i][j], a[i], b[j]);
        }
    }

    if (SPLIT) {
        const int head = (n0 + 64 * wn) >> 6;
        uint32_t* outw = reinterpret_cast<uint32_t*>(Sp);
#pragma unroll
        for (int i = 0; i < 2; i++) {
            int row = m0 + 32 * wm + 16 * i + g;
#pragma unroll
            for (int j = 0; j < 8; j++) {
                int d = 8 * j + 2 * t4;
                float2 bb2 = *reinterpret_cast<const float2*>(bias + n0 + 64 * wn + d);
                uint32_t hi, lo;
                int w0 = row * 1024 + head * 64 + (d >> 1);
                pack_hl(acc[i][j][0] + bb2.x, acc[i][j][1] + bb2.y, hi, lo);
                outw[w0] = hi; outw[w0 + 32] = lo;
                w0 += 8 * 1024;
                pack_hl(acc[i][j][2] + bb2.x, acc[i][j][3] + bb2.y, hi, lo);
                outw[w0] = hi; outw[w0 + 32] = lo;
            }
        }
    } else {
#pragma unroll
        for (int i = 0; i < 2; i++) {
            int row = m0 + 32 * wm + 16 * i + g;
#pragma unroll
            for (int j = 0; j < 8; j++) {
                int col = n0 + 64 * wn + 8 * j + 2 * t4;
                float2 bb2 = *reinterpret_cast<const float2*>(bias + col);
                float2 v0 = { acc[i][j][0] + bb2.x, acc[i][j][1] + bb2.y };
                float2 v1 = { acc[i][j][2] + bb2.x, acc[i][j][3] + bb2.y };
                *reinterpret_cast<float2*>(Cf + (size_t)row * E_ + col) = v0;
                *reinterpret_cast<float2*>(Cf + (size_t)(row + 8) * E_ + col) = v1;
            }
        }
    }
}

// ---------------- Flash attention: 128 threads, 4 warps x m32, 2 CTAs/SM ----------------
// QT=128, KT=64. smem words:
//   Q: [0, 8704)  rows 0..127, stride 68: [hi 32w | lo 32w | pad 4w]
//   K: 2 bufs @ 8704, each 64 x 68
//   V: 2 bufs @ 17408, each 128 x 36 (rows 0-63 hi, 64-127 lo)
#define FQT 128
#define FKT 64
#define QS_W 68
#define VS_W 36
#define KB0 8704
#define KBUF_W (64 * QS_W)
#define VB0 (KB0 + 2 * KBUF_W)
#define VBUF_W (128 * VS_W)
#define F_SMEM_BYTES ((VB0 + 2 * VBUF_W) * 4)   // 106496

__global__ __launch_bounds__(128, 2) void flash_mma(
    const __nv_bfloat16* __restrict__ Qg, const __nv_bfloat16* __restrict__ Kg,
    const __nv_bfloat16* __restrict__ Vg, uint32_t* __restrict__ Cw)
{
    extern __shared__ uint32_t smw[];
    const uint32_t smb = smem_u32(smw);
    const int tid = threadIdx.x;
    const int wid = tid >> 5, lane = tid & 31;
    const int g = lane >> 2, t4 = lane & 3;
    const int bz = blockIdx.z, hh = blockIdx.y;
    const int q0 = blockIdx.x * FQT;

    // ---- issue Q (one cp.async group) ----
    {
        const char* qg = (const char*)Qg + ((size_t)(bz * N_ + q0) * 2048 + hh * 128) * 2;
#pragma unroll
        for (int u = 0; u < 16; u++) {
            int c = tid + 128 * u;
            int row = c >> 4, p = c & 15;
            cp_async16(smb + (row * QS_W + p * 4) * 4, qg + (size_t)row * 4096 + p * 16);
        }
        cp_commit();
    }
    auto issue_kv = [&](int t) {
        const int b = t & 1;
        const char* kg = (const char*)Kg + ((size_t)(bz * N_ + t * 64) * 2048 + hh * 128) * 2;
        const char* vg = (const char*)Vg + ((size_t)(bz * N_ + t * 64) * 2048 + hh * 128) * 2;
#pragma unroll
        for (int u = 0; u < 8; u++) {
            int c = tid + 128 * u;
            int row = c >> 4, p = c & 15;
            cp_async16(smb + ((KB0 + b * KBUF_W) + row * QS_W + p * 4) * 4,
                       kg + (size_t)row * 4096 + p * 16);
        }
#pragma unroll
        for (int u = 0; u < 8; u++) {
            int c = tid + 128 * u;
            int row = c >> 4, p = c & 15;
            int part = p >> 3, k = p & 7;
            cp_async16(smb + ((VB0 + b * VBUF_W) + (part * 64 + row) * VS_W + k * 4) * 4,
                       vg + (size_t)row * 4096 + p * 16);
        }
        cp_commit();
    };

    issue_kv(0);
    asm volatile("cp.async.wait_group 1;" ::: "memory");   // Q resident
    __syncthreads();

    // ---- hoist Q-hi fragments ----
    const int qa_row = 32 * wid + (lane & 15);
    const int qa_cw  = 4 * (lane >> 4);
    uint32_t qh[2][4][4];
#pragma unroll
    for (int i = 0; i < 2; i++)
#pragma unroll
        for (int kc = 0; kc < 4; kc++)
            ldsm4(qh[i][kc], smb + ((qa_row + 16 * i) * QS_W + qa_cw + 8 * kc) * 4);

    float o[2][8][4], mrow[2][2], lrow[2][2];
#pragma unroll
    for (int i = 0; i < 2; i++) {
        mrow[i][0] = mrow[i][1] = -CUDART_INF_F;
        lrow[i][0] = lrow[i][1] = 0.0f;
#pragma unroll
        for (int j = 0; j < 8; j++)
#pragma unroll
            for (int q = 0; q < 4; q++) o[i][j][q] = 0.0f;
    }

    const int kb_row = (lane & 7) + 8 * (lane >> 4);
    const int kb_cw  = 4 * ((lane >> 3) & 1);
    const int tsel = lane >> 3;

    for (int t = 0; t < N_ / FKT; t++) {
        if (t + 1 < N_ / FKT) {
            issue_kv(t + 1);
            asm volatile("cp.async.wait_group 1;" ::: "memory");
        } else {
            asm volatile("cp.async.wait_group 0;" ::: "memory");
        }
        __syncthreads();
        const int koff = KB0 + (t & 1) * KBUF_W;
        const int voff = VB0 + (t & 1) * VBUF_W;

        // ---- S = Q Kt : (Qh+Ql)*Kh then Qh*Kl ----
        float s[2][8][4];
#pragma unroll
        for (int i = 0; i < 2; i++)
#pragma unroll
            for (int j = 0; j < 8; j++)
#pragma unroll
                for (int q = 0; q < 4; q++) s[i][j][q] = 0.0f;

#pragma unroll
        for (int kc = 0; kc < 4; kc++) {
            uint32_t kb[8][2];
#pragma unroll
            for (int jp = 0; jp < 4; jp++) {
                uint32_t r4[4];
                ldsm4(r4, smb + (koff + (kb_row + 16 * jp) * QS_W + kb_cw + 8 * kc) * 4);
                kb[2 * jp][0] = r4[0]; kb[2 * jp][1] = r4[1];
                kb[2 * jp + 1][0] = r4[2]; kb[2 * jp + 1][1] = r4[3];
            }
#pragma unroll
            for (int i = 0; i < 2; i++)
#pragma unroll
                for (int j = 0; j < 8; j++) mma16816(s[i][j], qh[i][kc], kb[j]);
            uint32_t ql[2][4];
#pragma unroll
            for (int i = 0; i < 2; i++)
                ldsm4(ql[i], smb + ((qa_row + 16 * i) * QS_W + 32 + qa_cw + 8 * kc) * 4);
#pragma unroll
            for (int i = 0; i < 2; i++)
#pragma unroll
                for (int j = 0; j < 8; j++) mma16816(s[i][j], ql[i], kb[j]);
        }
#pragma unroll
        for (int kc = 0; kc < 4; kc++) {
            uint32_t kb[8][2];
#pragma unroll
            for (int jp = 0; jp < 4; jp++) {
                uint32_t r4[4];
                ldsm4(r4, smb + (koff + (kb_row + 16 * jp) * QS_W + 32 + kb_cw + 8 * kc) * 4);
                kb[2 * jp][0] = r4[0]; kb[2 * jp][1] = r4[1];
                kb[2 * jp + 1][0] = r4[2]; kb[2 * jp + 1][1] = r4[3];
            }
#pragma unroll
            for (int i = 0; i < 2; i++)
#pragma unroll
                for (int j = 0; j < 8; j++) mma16816(s[i][j], qh[i][kc], kb[j]);
        }

        // ---- online softmax ----
#pragma unroll
        for (int i = 0; i < 2; i++) {
#pragma unroll
            for (int h = 0; h < 2; h++) {
                float mx = -CUDART_INF_F;
#pragma unroll
                for (int j = 0; j < 8; j++)
                    mx = fmaxf(mx, fmaxf(s[i][j][2 * h], s[i][j][2 * h + 1]));
                mx = fmaxf(mx, __shfl_xor_sync(0xFFFFFFFFu, mx, 1));
                mx = fmaxf(mx, __shfl_xor_sync(0xFFFFFFFFu, mx, 2));
                float mnew = fmaxf(mrow[i][h], mx);
                float alpha = __expf(mrow[i][h] - mnew);
                mrow[i][h] = mnew;
                float ls = 0.0f;
#pragma unroll
                for (int j = 0; j < 8; j++) {
                    float p0 = __expf(s[i][j][2 * h] - mnew);
                    float p1 = __expf(s[i][j][2 * h + 1] - mnew);
                    ls += p0 + p1;
                    s[i][j][2 * h] = p0; s[i][j][2 * h + 1] = p1;
                }
                ls += __shfl_xor_sync(0xFFFFFFFFu, ls, 1);
                ls += __shfl_xor_sync(0xFFFFFFFFu, ls, 2);
                lrow[i][h] = lrow[i][h] * alpha + ls;
#pragma unroll
                for (int j = 0; j < 8; j++) {
                    o[i][j][2 * h] *= alpha; o[i][j][2 * h + 1] *= alpha;
                }
            }
        }

        // ---- PV: per-kc pack (low reg pressure) + Vh(hi+lo P) + Vl(hi P) ----
#pragma unroll
        for (int kc = 0; kc < 4; kc++) {
            uint32_t ph[2][2], phB[2][2], pl[2][2], plB[2][2];
#pragma unroll
            for (int i = 0; i < 2; i++)
#pragma unroll
                for (int jj = 0; jj < 2; jj++) {
                    int j = 2 * kc + jj;
                    pack_hl(s[i][j][0], s[i][j][1], ph[i][jj], pl[i][jj]);
                    pack_hl(s[i][j][2], s[i][j][3], phB[i][jj], plB[i][jj]);
                }
            uint32_t vb[8][2];
#pragma unroll
            for (int jj = 0; jj < 8; jj += 2) {
                uint32_t r4[4];
                int row = 16 * kc + 8 * (tsel & 1) + (lane & 7);
                ldsm4t(r4, smb + (voff + row * VS_W) * 4 + 16 * (jj + (tsel >> 1)));
                vb[jj][0] = r4[0]; vb[jj][1] = r4[1];
                vb[jj + 1][0] = r4[2]; vb[jj + 1][1] = r4[3];
            }
#pragma unroll
            for (int i = 0; i < 2; i++) {
                uint32_t pa[4] = { ph[i][0], phB[i][0], ph[i][1], phB[i][1] };
#pragma unroll
                for (int j = 0; j < 8; j++) mma16816(o[i][j], pa, vb[j]);
            }
#pragma unroll
            for (int i = 0; i < 2; i++) {
                uint32_t pa[4] = { pl[i][0], plB[i][0], pl[i][1], plB[i][1] };
#pragma unroll
                for (int j = 0; j < 8; j++) mma16816(o[i][j], pa, vb[j]);
            }
#pragma unroll
            for (int jj = 0; jj < 8; jj += 2) {
                uint32_t r4[4];
                int row = 64 + 16 * kc + 8 * (tsel & 1) + (lane & 7);
                ldsm4t(r4, smb + (voff + row * VS_W) * 4 + 16 * (jj + (tsel >> 1)));
                vb[jj][0] = r4[0]; vb[jj][1] = r4[1];
                vb[jj + 1][0] = r4[2]; vb[jj + 1][1] = r4[3];
            }
#pragma unroll
            for (int i = 0; i < 2; i++) {
                uint32_t pa[4] = { ph[i][0], phB[i][0], ph[i][1], phB[i][1] };
#pragma unroll
                for (int j = 0; j < 8; j++) mma16816(o[i][j], pa, vb[j]);
            }
        }
        __syncthreads();
    }

    // ---- epilogue: write split context into [hi|lo|hi] (1536 words/row) ----
#pragma unroll
    for (int i = 0; i < 2; i++) {
        float inv0 = 1.0f / (lrow[i][0] * 32.0f);
        float inv1 = 1.0f / (lrow[i][1] * 32.0f);
        int row = bz * N_ + q0 + 32 * wid + 16 * i + g;
#pragma unroll
        for (int j = 0; j < 8; j++) {
            int cw = (hh * 64 + 8 * j + 2 * t4) >> 1;
            uint32_t hi, lo;
            int base = row * 1536;
            pack_hl(o[i][j][0] * inv0, o[i][j][1] * inv0, hi, lo);
            Cw[base + cw] = hi; Cw[base + 512 + cw] = lo; Cw[base + 1024 + cw] = hi;
            base = (row + 8) * 1536;
            pack_hl(o[i][j][2] * inv1, o[i][j][3] * inv1, hi, lo);
            Cw[base + cw] = hi; Cw[base + 512 + cw] = lo; Cw[base + 1024 + cw] = hi;
        }
    }
}

// ---------------- launcher ----------------
extern "C" void kernel_launch(void* const* d_in, const int* in_sizes, int n_in,
                              void* d_out, int out_size)
{
    const float* x  = (const float*)d_in[0];
    const float* Wq = (const float*)d_in[1];
    const float* bq = (const float*)d_in[2];
    const float* Wk = (const float*)d_in[3];
    const float* bk = (const float*)d_in[4];
    const float* Wv = (const float*)d_in[5];
    const float* bv = (const float*)d_in[6];
    const float* Wo = (const float*)d_in[7];
    const float* bo = (const float*)d_in[8];
    float* out = (float*)d_out;

    cudaFuncSetAttribute(gemm_mma_t<1>, cudaFuncAttributeMaxDynamicSharedMemorySize, G_SMEM_BYTES);
    cudaFuncSetAttribute(gemm_mma_t<0>, cudaFuncAttributeMaxDynamicSharedMemorySize, G_SMEM_BYTES);
    cudaFuncSetAttribute(flash_mma, cudaFuncAttributeMaxDynamicSharedMemorySize, F_SMEM_BYTES);

    __nv_bfloat16 *Qs, *Ks, *Vs, *xe, *ce, *wqe, *wke, *wve, *woe;
    cudaGetSymbolAddress((void**)&Qs, g_Qs);
    cudaGetSymbolAddress((void**)&Ks, g_Ks);
    cudaGetSymbolAddress((void**)&Vs, g_Vs);
    cudaGetSymbolAddress((void**)&xe, g_xext);
    cudaGetSymbolAddress((void**)&ce, g_cext);
    cudaGetSymbolAddress((void**)&wqe, g_wqext);
    cudaGetSymbolAddress((void**)&wke, g_wkext);
    cudaGetSymbolAddress((void**)&wve, g_wvext);
    cudaGetSymbolAddress((void**)&woe, g_woext);

    cvt_x<<<M_, 256>>>(x, xe);
    dim3 wgrid(E_, 4);
    cvt_w4<<<wgrid, 256>>>(Wq, Wk, Wv, Wo, wqe, wke, wve, woe);

    dim3 ggrid3(E_ / 128, M_ / 128, 3);
    gemm_mma_t<1><<<ggrid3, 256, G_SMEM_BYTES>>>(
        xe, wqe, wke, wve, bq, bk, bv, nullptr, Qs, Ks, Vs);

    dim3 fgrid(N_ / FQT, H_, B_);
    flash_mma<<<fgrid, 128, F_SMEM_BYTES>>>(Qs, Ks, Vs, (uint32_t*)ce);

    dim3 ggrid1(E_ / 128, M_ / 128, 1);
    gemm_mma_t<0><<<ggrid1, 256, G_SMEM_BYTES>>>(
        ce, woe, woe, woe, bo, bo, bo, out, nullptr, nullptr, nullptr);
}

// round 9
// speedup vs baseline: 3.9794x; 1.1451x over previous
#include <cuda_runtime.h>
#include <cuda_bf16.h>
#include <cuda_fp16.h>
#include <math_constants.h>
#include <cstdint>

#define B_  2
#define N_  2048
#define E_  1024
#define H_  16
#define D_  64
#define M_  (B_ * N_)
#define K3_ 3072

// ---------------- scratch ----------------
__device__ __half g_Qs[M_ * 2048];            // fp16 [row][head][64hi|64lo]
__device__ __half g_Ks[M_ * 2048];
__device__ __half g_Vs[M_ * 2048];
__device__ __nv_bfloat16 g_xext[M_ * K3_];    // [hi|lo|hi]
__device__ __nv_bfloat16 g_cext[M_ * K3_];    // [hi|lo|hi], written by flash
__device__ __nv_bfloat16 g_wqext[E_ * K3_];   // [hi|hi|lo]
__device__ __nv_bfloat16 g_wkext[E_ * K3_];
__device__ __nv_bfloat16 g_wvext[E_ * K3_];
__device__ __nv_bfloat16 g_woext[E_ * K3_];

// ---------------- helpers ----------------
__device__ __forceinline__ uint32_t smem_u32(const void* p) {
    uint32_t a;
    asm("{ .reg .u64 t; cvta.to.shared.u64 t, %1; cvt.u32.u64 %0, t; }" : "=r"(a) : "l"(p));
    return a;
}
// bf16 mma (projection GEMMs)
__device__ __forceinline__ void mma16816(float* c, const uint32_t* a, const uint32_t* b) {
    asm volatile(
        "mma.sync.aligned.m16n8k16.row.col.f32.bf16.bf16.f32 "
        "{%0,%1,%2,%3}, {%4,%5,%6,%7}, {%8,%9}, {%0,%1,%2,%3};"
        : "+f"(c[0]), "+f"(c[1]), "+f"(c[2]), "+f"(c[3])
        : "r"(a[0]), "r"(a[1]), "r"(a[2]), "r"(a[3]), "r"(b[0]), "r"(b[1]));
}
// fp16 mma (attention)
__device__ __forceinline__ void mma16816f(float* c, const uint32_t* a, const uint32_t* b) {
    asm volatile(
        "mma.sync.aligned.m16n8k16.row.col.f32.f16.f16.f32 "
        "{%0,%1,%2,%3}, {%4,%5,%6,%7}, {%8,%9}, {%0,%1,%2,%3};"
        : "+f"(c[0]), "+f"(c[1]), "+f"(c[2]), "+f"(c[3])
        : "r"(a[0]), "r"(a[1]), "r"(a[2]), "r"(a[3]), "r"(b[0]), "r"(b[1]));
}
__device__ __forceinline__ void ldsm4(uint32_t* r, uint32_t addr) {
    asm volatile("ldmatrix.sync.aligned.m8n8.x4.shared.b16 {%0,%1,%2,%3}, [%4];"
        : "=r"(r[0]), "=r"(r[1]), "=r"(r[2]), "=r"(r[3]) : "r"(addr));
}
__device__ __forceinline__ void ldsm4t(uint32_t* r, uint32_t addr) {
    asm volatile("ldmatrix.sync.aligned.m8n8.x4.trans.shared.b16 {%0,%1,%2,%3}, [%4];"
        : "=r"(r[0]), "=r"(r[1]), "=r"(r[2]), "=r"(r[3]) : "r"(addr));
}
__device__ __forceinline__ void cp_async16(uint32_t s, const void* g) {
    asm volatile("cp.async.cg.shared.global [%0], [%1], 16;" :: "r"(s), "l"(g) : "memory");
}
__device__ __forceinline__ void cp_commit() {
    asm volatile("cp.async.commit_group;" ::: "memory");
}
__device__ __forceinline__ void pack_hl(float x, float y, uint32_t& hi, uint32_t& lo) {
    __nv_bfloat162 h2 = __floats2bfloat162_rn(x, y);
    float rx = x - __bfloat162float(h2.x);
    float ry = y - __bfloat162float(h2.y);
    __nv_bfloat162 l2 = __floats2bfloat162_rn(rx, ry);
    hi = *reinterpret_cast<uint32_t*>(&h2);
    lo = *reinterpret_cast<uint32_t*>(&l2);
}
__device__ __forceinline__ void pack_hl_f16(float x, float y, uint32_t& hi, uint32_t& lo) {
    __half2 h2 = __floats2half2_rn(x, y);
    float rx = x - __half2float(__low2half(h2));
    float ry = y - __half2float(__high2half(h2));
    __half2 l2 = __floats2half2_rn(rx, ry);
    hi = *reinterpret_cast<uint32_t*>(&h2);
    lo = *reinterpret_cast<uint32_t*>(&l2);
}

// ---------------- x conversion: [hi|lo|hi] bf16 ----------------
__global__ __launch_bounds__(256) void cvt_x(
    const float* __restrict__ in, __nv_bfloat16* __restrict__ out)
{
    int idx = blockIdx.x * 256 + threadIdx.x;
    int r = idx >> 8;
    int c = (idx & 255) << 2;
    float4 v = *reinterpret_cast<const float4*>(in + (size_t)r * E_ + c);
    uint32_t h0, l0, h1, l1;
    pack_hl(v.x, v.y, h0, l0);
    pack_hl(v.z, v.w, h1, l1);
    uint32_t* o = reinterpret_cast<uint32_t*>(out + (size_t)r * K3_);
    int cw = c >> 1;
    o[cw] = h0; o[cw + 1] = h1;
    o[512 + cw] = l0; o[512 + cw + 1] = l1;
    o[1024 + cw] = h0; o[1024 + cw + 1] = h1;
}

// ---------------- weight conversion (4 fused): [hi|hi|lo] bf16 ----------------
__global__ __launch_bounds__(256) void cvt_w4(
    const float* __restrict__ W0, const float* __restrict__ W1,
    const float* __restrict__ W2, const float* __restrict__ W3,
    __nv_bfloat16* __restrict__ O0, __nv_bfloat16* __restrict__ O1,
    __nv_bfloat16* __restrict__ O2, __nv_bfloat16* __restrict__ O3)
{
    int sel = blockIdx.y;
    const float* in = sel == 0 ? W0 : sel == 1 ? W1 : sel == 2 ? W2 : W3;
    __nv_bfloat16* out = sel == 0 ? O0 : sel == 1 ? O1 : sel == 2 ? O2 : O3;
    int idx = blockIdx.x * 256 + threadIdx.x;
    int r = idx >> 8;
    int c = (idx & 255) << 2;
    float4 v = *reinterpret_cast<const float4*>(in + (size_t)r * E_ + c);
    uint32_t h0, l0, h1, l1;
    pack_hl(v.x, v.y, h0, l0);
    pack_hl(v.z, v.w, h1, l1);
    uint32_t* o = reinterpret_cast<uint32_t*>(out + (size_t)r * K3_);
    int cw = c >> 1;
    o[cw] = h0; o[cw + 1] = h1;
    o[512 + cw] = h0;  o[512 + cw + 1] = h1;
    o[1024 + cw] = l0; o[1024 + cw + 1] = l1;
}

// ---------------- HMMA NT GEMM (bf16, ldmatrix), 4-stage, 2 CTAs/SM ----------------
#define GS_W 20
#define G_STAGE_W (256 * GS_W)
#define G_SMEM_BYTES (4 * G_STAGE_W * 4)

template<int SPLIT>
__global__ __launch_bounds__(256, 2) void gemm_mma_t(
    const __nv_bfloat16* __restrict__ A,
    const __nv_bfloat16* __restrict__ W0, const __nv_bfloat16* __restrict__ W1,
    const __nv_bfloat16* __restrict__ W2,
    const float* __restrict__ b0, const float* __restrict__ b1, const float* __restrict__ b2,
    float* __restrict__ Cf,
    __half* __restrict__ S0, __half* __restrict__ S1, __half* __restrict__ S2)
{
    extern __shared__ uint32_t smw[];
    const int z = blockIdx.z;
    const __nv_bfloat16* W = (z == 0) ? W0 : (z == 1) ? W1 : W2;
    const float* bias = (z == 0) ? b0 : (z == 1) ? b1 : b2;
    __half* Sp = (z == 0) ? S0 : (z == 1) ? S1 : S2;

    const int tid = threadIdx.x;
    const int wid = tid >> 5, lane = tid & 31;
    const int g = lane >> 2, t4 = lane & 3;
    const int wm = wid & 3, wn = wid >> 2;
    const int m0 = blockIdx.y * 128;
    const int n0 = blockIdx.x * 128;
    const int NT = K3_ / 32;
    const uint32_t smb = smem_u32(smw);

    auto issue = [&](int kt) {
        const int sb = (kt & 3) * G_STAGE_W;
#pragma unroll
        for (int u = 0; u < 2; u++) {
            int c = tid + 256 * u;
            int row = c >> 2, k4 = c & 3;
            uint32_t sa = smb + (sb + row * GS_W + k4 * 4) * 4;
            cp_async16(sa, A + (size_t)(m0 + row) * K3_ + kt * 32 + k4 * 8);
            cp_async16(sa + 128 * GS_W * 4, W + (size_t)(n0 + row) * K3_ + kt * 32 + k4 * 8);
        }
        cp_commit();
    };

    float acc[2][8][4];
#pragma unroll
    for (int i = 0; i < 2; i++)
#pragma unroll
        for (int j = 0; j < 8; j++)
#pragma unroll
            for (int q = 0; q < 4; q++) acc[i][j][q] = 0.0f;

    issue(0); issue(1); issue(2);

    const int a_row = 32 * wm + (lane & 15);
    const int a_cw  = 4 * (lane >> 4);
    const int b_row = 64 * wn + (lane & 7) + 8 * (lane >> 4);
    const int b_cw  = 4 * ((lane >> 3) & 1);

    for (int kt = 0; kt < NT; kt++) {
        if (kt < NT - 2)       asm volatile("cp.async.wait_group 2;" ::: "memory");
        else if (kt == NT - 2) asm volatile("cp.async.wait_group 1;" ::: "memory");
        else                   asm volatile("cp.async.wait_group 0;" ::: "memory");
        __syncthreads();
        if (kt + 3 < NT) issue(kt + 3);

        const int sb = (kt & 3) * G_STAGE_W;
        const int bb = sb + 128 * GS_W;
#pragma unroll
        for (int kk = 0; kk < 2; kk++) {
            uint32_t a[2][4], b[8][2];
#pragma unroll
            for (int i = 0; i < 2; i++)
                ldsm4(a[i], smb + (sb + (a_row + 16 * i) * GS_W + a_cw + 8 * kk) * 4);
#pragma unroll
            for (int jp = 0; jp < 4; jp++) {
                uint32_t r4[4];
                ldsm4(r4, smb + (bb + (b_row + 16 * jp) * GS_W + b_cw + 8 * kk) * 4);
                b[2 * jp][0] = r4[0]; b[2 * jp][1] = r4[1];
                b[2 * jp + 1][0] = r4[2]; b[2 * jp + 1][1] = r4[3];
            }
#pragma unroll
            for (int i = 0; i < 2; i++)
#pragma unroll
                for (int j = 0; j < 8; j++) mma16816(acc[i][j], a[i], b[j]);
        }
    }

    if (SPLIT) {
        const int head = (n0 + 64 * wn) >> 6;
        uint32_t* outw = reinterpret_cast<uint32_t*>(Sp);
#pragma unroll
        for (int i = 0; i < 2; i++) {
            int row = m0 + 32 * wm + 16 * i + g;
#pragma unroll
            for (int j = 0; j < 8; j++) {
                int d = 8 * j + 2 * t4;
                float2 bb2 = *reinterpret_cast<const float2*>(bias + n0 + 64 * wn + d);
                uint32_t hi, lo;
                int w0 = row * 1024 + head * 64 + (d >> 1);
                pack_hl_f16(acc[i][j][0] + bb2.x, acc[i][j][1] + bb2.y, hi, lo);
                outw[w0] = hi; outw[w0 + 32] = lo;
                w0 += 8 * 1024;
                pack_hl_f16(acc[i][j][2] + bb2.x, acc[i][j][3] + bb2.y, hi, lo);
                outw[w0] = hi; outw[w0 + 32] = lo;
            }
        }
    } else {
#pragma unroll
        for (int i = 0; i < 2; i++) {
            int row = m0 + 32 * wm + 16 * i + g;
#pragma unroll
            for (int j = 0; j < 8; j++) {
                int col = n0 + 64 * wn + 8 * j + 2 * t4;
                float2 bb2 = *reinterpret_cast<const float2*>(bias + col);
                float2 v0 = { acc[i][j][0] + bb2.x, acc[i][j][1] + bb2.y };
                float2 v1 = { acc[i][j][2] + bb2.x, acc[i][j][3] + bb2.y };
                *reinterpret_cast<float2*>(Cf + (size_t)row * E_ + col) = v0;
                *reinterpret_cast<float2*>(Cf + (size_t)(row + 8) * E_ + col) = v1;
            }
        }
    }
}

// ---------------- Flash attention: fp16 2-term, 128 threads, 4 warps x m32 ----------------
// QT=128, KT=64. smem words:
//   Q: [0, 8704)  rows 0..127, stride 68: [hi 32w | lo 32w | pad 4w]
//   K: 2 bufs @ 8704, each 64 x 36 (hi only)
//   V: 2 bufs @ 13312, each 64 x 36 (hi only)
#define FQT 128
#define FKT 64
#define QS_W 68
#define KS_W 36
#define VS_W 36
#define KB0 8704
#define KBUF_W (64 * KS_W)            // 2304
#define VB0 (KB0 + 2 * KBUF_W)        // 13312
#define VBUF_W (64 * VS_W)            // 2304
#define F_SMEM_BYTES ((VB0 + 2 * VBUF_W) * 4)   // 71680

__global__ __launch_bounds__(128, 2) void flash_mma(
    const __half* __restrict__ Qg, const __half* __restrict__ Kg,
    const __half* __restrict__ Vg, uint32_t* __restrict__ Cw)
{
    extern __shared__ uint32_t smw[];
    const uint32_t smb = smem_u32(smw);
    const int tid = threadIdx.x;
    const int wid = tid >> 5, lane = tid & 31;
    const int g = lane >> 2, t4 = lane & 3;
    const int bz = blockIdx.z, hh = blockIdx.y;
    const int q0 = blockIdx.x * FQT;

    // ---- issue Q (hi+lo, one group): 2048 chunks / 128 thr ----
    {
        const char* qg = (const char*)Qg + ((size_t)(bz * N_ + q0) * 2048 + hh * 128) * 2;
#pragma unroll
        for (int u = 0; u < 16; u++) {
            int c = tid + 128 * u;
            int row = c >> 4, p = c & 15;
            cp_async16(smb + (row * QS_W + p * 4) * 4, qg + (size_t)row * 4096 + p * 16);
        }
        cp_commit();
    }
    // ---- issue K/V hi-only: 512 chunks each ----
    auto issue_kv = [&](int t) {
        const int b = t & 1;
        const char* kg = (const char*)Kg + ((size_t)(bz * N_ + t * 64) * 2048 + hh * 128) * 2;
        const char* vg = (const char*)Vg + ((size_t)(bz * N_ + t * 64) * 2048 + hh * 128) * 2;
#pragma unroll
        for (int u = 0; u < 4; u++) {
            int c = tid + 128 * u;
            int row = c >> 3, p = c & 7;
            cp_async16(smb + ((KB0 + b * KBUF_W) + row * KS_W + p * 4) * 4,
                       kg + (size_t)row * 4096 + p * 16);
        }
#pragma unroll
        for (int u = 0; u < 4; u++) {
            int c = tid + 128 * u;
            int row = c >> 3, p = c & 7;
            cp_async16(smb + ((VB0 + b * VBUF_W) + row * VS_W + p * 4) * 4,
                       vg + (size_t)row * 4096 + p * 16);
        }
        cp_commit();
    };

    issue_kv(0);
    asm volatile("cp.async.wait_group 1;" ::: "memory");   // Q resident
    __syncthreads();

    // ---- hoist Q-hi fragments ----
    const int qa_row = 32 * wid + (lane & 15);
    const int qa_cw  = 4 * (lane >> 4);
    uint32_t qh[2][4][4];
#pragma unroll
    for (int i = 0; i < 2; i++)
#pragma unroll
        for (int kc = 0; kc < 4; kc++)
            ldsm4(qh[i][kc], smb + ((qa_row + 16 * i) * QS_W + qa_cw + 8 * kc) * 4);

    float o[2][8][4], mrow[2][2], lrow[2][2];
#pragma unroll
    for (int i = 0; i < 2; i++) {
        mrow[i][0] = mrow[i][1] = -CUDART_INF_F;
        lrow[i][0] = lrow[i][1] = 0.0f;
#pragma unroll
        for (int j = 0; j < 8; j++)
#pragma unroll
            for (int q = 0; q < 4; q++) o[i][j][q] = 0.0f;
    }

    const int kb_row = (lane & 7) + 8 * (lane >> 4);
    const int kb_cw  = 4 * ((lane >> 3) & 1);
    const int tsel = lane >> 3;

    for (int t = 0; t < N_ / FKT; t++) {
        if (t + 1 < N_ / FKT) {
            issue_kv(t + 1);
            asm volatile("cp.async.wait_group 1;" ::: "memory");
        } else {
            asm volatile("cp.async.wait_group 0;" ::: "memory");
        }
        __syncthreads();
        const int koff = KB0 + (t & 1) * KBUF_W;
        const int voff = VB0 + (t & 1) * VBUF_W;

        // ---- S = (Qh + Ql) Kh : 2 passes per kc ----
        float s[2][8][4];
#pragma unroll
        for (int i = 0; i < 2; i++)
#pragma unroll
            for (int j = 0; j < 8; j++)
#pragma unroll
                for (int q = 0; q < 4; q++) s[i][j][q] = 0.0f;

#pragma unroll
        for (int kc = 0; kc < 4; kc++) {
            uint32_t kb[8][2];
#pragma unroll
            for (int jp = 0; jp < 4; jp++) {
                uint32_t r4[4];
                ldsm4(r4, smb + (koff + (kb_row + 16 * jp) * KS_W + kb_cw + 8 * kc) * 4);
                kb[2 * jp][0] = r4[0]; kb[2 * jp][1] = r4[1];
                kb[2 * jp + 1][0] = r4[2]; kb[2 * jp + 1][1] = r4[3];
            }
#pragma unroll
            for (int i = 0; i < 2; i++)
#pragma unroll
                for (int j = 0; j < 8; j++) mma16816f(s[i][j], qh[i][kc], kb[j]);
            uint32_t ql[2][4];
#pragma unroll
            for (int i = 0; i < 2; i++)
                ldsm4(ql[i], smb + ((qa_row + 16 * i) * QS_W + 32 + qa_cw + 8 * kc) * 4);
#pragma unroll
            for (int i = 0; i < 2; i++)
#pragma unroll
                for (int j = 0; j < 8; j++) mma16816f(s[i][j], ql[i], kb[j]);
        }

        // ---- online softmax ----
#pragma unroll
        for (int i = 0; i < 2; i++) {
#pragma unroll
            for (int h = 0; h < 2; h++) {
                float mx = -CUDART_INF_F;
#pragma unroll
                for (int j = 0; j < 8; j++)
                    mx = fmaxf(mx, fmaxf(s[i][j][2 * h], s[i][j][2 * h + 1]));
                mx = fmaxf(mx, __shfl_xor_sync(0xFFFFFFFFu, mx, 1));
                mx = fmaxf(mx, __shfl_xor_sync(0xFFFFFFFFu, mx, 2));
                float mnew = fmaxf(mrow[i][h], mx);
                float alpha = __expf(mrow[i][h] - mnew);
                mrow[i][h] = mnew;
                float ls = 0.0f;
#pragma unroll
                for (int j = 0; j < 8; j++) {
                    float p0 = __expf(s[i][j][2 * h] - mnew);
                    float p1 = __expf(s[i][j][2 * h + 1] - mnew);
                    ls += p0 + p1;
                    s[i][j][2 * h] = p0; s[i][j][2 * h + 1] = p1;
                }
                ls += __shfl_xor_sync(0xFFFFFFFFu, ls, 1);
                ls += __shfl_xor_sync(0xFFFFFFFFu, ls, 2);
                lrow[i][h] = lrow[i][h] * alpha + ls;
#pragma unroll
                for (int j = 0; j < 8; j++) {
                    o[i][j][2 * h] *= alpha; o[i][j][2 * h + 1] *= alpha;
                }
            }
        }

        // ---- PV: (Ph + Pl) Vh : per-kc pack + 2 passes ----
#pragma unroll
        for (int kc = 0; kc < 4; kc++) {
            uint32_t ph[2][2], phB[2][2], pl[2][2], plB[2][2];
#pragma unroll
            for (int i = 0; i < 2; i++)
#pragma unroll
                for (int jj = 0; jj < 2; jj++) {
                    int j = 2 * kc + jj;
                    pack_hl_f16(s[i][j][0], s[i][j][1], ph[i][jj], pl[i][jj]);
                    pack_hl_f16(s[i][j][2], s[i][j][3], phB[i][jj], plB[i][jj]);
                }
            uint32_t vb[8][2];
#pragma unroll
            for (int jj = 0; jj < 8; jj += 2) {
                uint32_t r4[4];
                int row = 16 * kc + 8 * (tsel & 1) + (lane & 7);
                ldsm4t(r4, smb + (voff + row * VS_W) * 4 + 16 * (jj + (tsel >> 1)));
                vb[jj][0] = r4[0]; vb[jj][1] = r4[1];
                vb[jj + 1][0] = r4[2]; vb[jj + 1][1] = r4[3];
            }
#pragma unroll
            for (int i = 0; i < 2; i++) {
                uint32_t pa[4] = { ph[i][0], phB[i][0], ph[i][1], phB[i][1] };
#pragma unroll
                for (int j = 0; j < 8; j++) mma16816f(o[i][j], pa, vb[j]);
            }
#pragma unroll
            for (int i = 0; i < 2; i++) {
                uint32_t pa[4] = { pl[i][0], plB[i][0], pl[i][1], plB[i][1] };
#pragma unroll
                for (int j = 0; j < 8; j++) mma16816f(o[i][j], pa, vb[j]);
            }
        }
        __syncthreads();
    }

    // ---- epilogue: write bf16 split context into [hi|lo|hi] ----
#pragma unroll
    for (int i = 0; i < 2; i++) {
        float inv0 = 1.0f / (lrow[i][0] * 32.0f);
        float inv1 = 1.0f / (lrow[i][1] * 32.0f);
        int row = bz * N_ + q0 + 32 * wid + 16 * i + g;
#pragma unroll
        for (int j = 0; j < 8; j++) {
            int cw = (hh * 64 + 8 * j + 2 * t4) >> 1;
            uint32_t hi, lo;
            int base = row * 1536;
            pack_hl(o[i][j][0] * inv0, o[i][j][1] * inv0, hi, lo);
            Cw[base + cw] = hi; Cw[base + 512 + cw] = lo; Cw[base + 1024 + cw] = hi;
            base = (row + 8) * 1536;
            pack_hl(o[i][j][2] * inv1, o[i][j][3] * inv1, hi, lo);
            Cw[base + cw] = hi; Cw[base + 512 + cw] = lo; Cw[base + 1024 + cw] = hi;
        }
    }
}

// ---------------- launcher ----------------
extern "C" void kernel_launch(void* const* d_in, const int* in_sizes, int n_in,
                              void* d_out, int out_size)
{
    const float* x  = (const float*)d_in[0];
    const float* Wq = (const float*)d_in[1];
    const float* bq = (const float*)d_in[2];
    const float* Wk = (const float*)d_in[3];
    const float* bk = (const float*)d_in[4];
    const float* Wv = (const float*)d_in[5];
    const float* bv = (const float*)d_in[6];
    const float* Wo = (const float*)d_in[7];
    const float* bo = (const float*)d_in[8];
    float* out = (float*)d_out;

    cudaFuncSetAttribute(gemm_mma_t<1>, cudaFuncAttributeMaxDynamicSharedMemorySize, G_SMEM_BYTES);
    cudaFuncSetAttribute(gemm_mma_t<0>, cudaFuncAttributeMaxDynamicSharedMemorySize, G_SMEM_BYTES);
    cudaFuncSetAttribute(flash_mma, cudaFuncAttributeMaxDynamicSharedMemorySize, F_SMEM_BYTES);

    __half *Qs, *Ks, *Vs;
    __nv_bfloat16 *xe, *ce, *wqe, *wke, *wve, *woe;
    cudaGetSymbolAddress((void**)&Qs, g_Qs);
    cudaGetSymbolAddress((void**)&Ks, g_Ks);
    cudaGetSymbolAddress((void**)&Vs, g_Vs);
    cudaGetSymbolAddress((void**)&xe, g_xext);
    cudaGetSymbolAddress((void**)&ce, g_cext);
    cudaGetSymbolAddress((void**)&wqe, g_wqext);
    cudaGetSymbolAddress((void**)&wke, g_wkext);
    cudaGetSymbolAddress((void**)&wve, g_wvext);
    cudaGetSymbolAddress((void**)&woe, g_woext);

    cvt_x<<<M_, 256>>>(x, xe);
    dim3 wgrid(E_, 4);
    cvt_w4<<<wgrid, 256>>>(Wq, Wk, Wv, Wo, wqe, wke, wve, woe);

    dim3 ggrid3(E_ / 128, M_ / 128, 3);
    gemm_mma_t<1><<<ggrid3, 256, G_SMEM_BYTES>>>(
        xe, wqe, wke, wve, bq, bk, bv, nullptr, Qs, Ks, Vs);

    dim3 fgrid(N_ / FQT, H_, B_);
    flash_mma<<<fgrid, 128, F_SMEM_BYTES>>>(Qs, Ks, Vs, (uint32_t*)ce);

    dim3 ggrid1(E_ / 128, M_ / 128, 1);
    gemm_mma_t<0><<<ggrid1, 256, G_SMEM_BYTES>>>(
        ce, woe, woe, woe, bo, bo, bo, out, nullptr, nullptr, nullptr);
}

// round 10
// speedup vs baseline: 3.9919x; 1.0032x over previous
#include <cuda_runtime.h>
#include <cuda_bf16.h>
#include <cuda_fp16.h>
#include <math_constants.h>
#include <cstdint>

#define B_  2
#define N_  2048
#define E_  1024
#define H_  16
#define D_  64
#define M_  (B_ * N_)
#define K3_ 3072

// ---------------- scratch ----------------
__device__ __half g_Qs[M_ * 2048];            // fp16 [row][head][64hi|64lo]
__device__ __half g_Ks[M_ * 2048];
__device__ __half g_Vs[M_ * 2048];
__device__ __nv_bfloat16 g_xext[M_ * K3_];    // [hi|lo|hi]
__device__ __nv_bfloat16 g_cext[M_ * K3_];    // [hi|lo|hi], written by flash
__device__ __nv_bfloat16 g_wqext[E_ * K3_];   // [hi|hi|lo]
__device__ __nv_bfloat16 g_wkext[E_ * K3_];
__device__ __nv_bfloat16 g_wvext[E_ * K3_];
__device__ __nv_bfloat16 g_woext[E_ * K3_];

// ---------------- helpers ----------------
__device__ __forceinline__ uint32_t smem_u32(const void* p) {
    uint32_t a;
    asm("{ .reg .u64 t; cvta.to.shared.u64 t, %1; cvt.u32.u64 %0, t; }" : "=r"(a) : "l"(p));
    return a;
}
// bf16 mma (projection GEMMs)
__device__ __forceinline__ void mma16816(float* c, const uint32_t* a, const uint32_t* b) {
    asm volatile(
        "mma.sync.aligned.m16n8k16.row.col.f32.bf16.bf16.f32 "
        "{%0,%1,%2,%3}, {%4,%5,%6,%7}, {%8,%9}, {%0,%1,%2,%3};"
        : "+f"(c[0]), "+f"(c[1]), "+f"(c[2]), "+f"(c[3])
        : "r"(a[0]), "r"(a[1]), "r"(a[2]), "r"(a[3]), "r"(b[0]), "r"(b[1]));
}
// fp16 mma (attention)
__device__ __forceinline__ void mma16816f(float* c, const uint32_t* a, const uint32_t* b) {
    asm volatile(
        "mma.sync.aligned.m16n8k16.row.col.f32.f16.f16.f32 "
        "{%0,%1,%2,%3}, {%4,%5,%6,%7}, {%8,%9}, {%0,%1,%2,%3};"
        : "+f"(c[0]), "+f"(c[1]), "+f"(c[2]), "+f"(c[3])
        : "r"(a[0]), "r"(a[1]), "r"(a[2]), "r"(a[3]), "r"(b[0]), "r"(b[1]));
}
__device__ __forceinline__ void ldsm4(uint32_t* r, uint32_t addr) {
    asm volatile("ldmatrix.sync.aligned.m8n8.x4.shared.b16 {%0,%1,%2,%3}, [%4];"
        : "=r"(r[0]), "=r"(r[1]), "=r"(r[2]), "=r"(r[3]) : "r"(addr));
}
__device__ __forceinline__ void ldsm4t(uint32_t* r, uint32_t addr) {
    asm volatile("ldmatrix.sync.aligned.m8n8.x4.trans.shared.b16 {%0,%1,%2,%3}, [%4];"
        : "=r"(r[0]), "=r"(r[1]), "=r"(r[2]), "=r"(r[3]) : "r"(addr));
}
__device__ __forceinline__ void cp_async16(uint32_t s, const void* g) {
    asm volatile("cp.async.cg.shared.global [%0], [%1], 16;" :: "r"(s), "l"(g) : "memory");
}
__device__ __forceinline__ void cp_commit() {
    asm volatile("cp.async.commit_group;" ::: "memory");
}
__device__ __forceinline__ void pack_hl(float x, float y, uint32_t& hi, uint32_t& lo) {
    __nv_bfloat162 h2 = __floats2bfloat162_rn(x, y);
    float rx = x - __bfloat162float(h2.x);
    float ry = y - __bfloat162float(h2.y);
    __nv_bfloat162 l2 = __floats2bfloat162_rn(rx, ry);
    hi = *reinterpret_cast<uint32_t*>(&h2);
    lo = *reinterpret_cast<uint32_t*>(&l2);
}
__device__ __forceinline__ void pack_hl_f16(float x, float y, uint32_t& hi, uint32_t& lo) {
    __half2 h2 = __floats2half2_rn(x, y);
    float rx = x - __half2float(__low2half(h2));
    float ry = y - __half2float(__high2half(h2));
    __half2 l2 = __floats2half2_rn(rx, ry);
    hi = *reinterpret_cast<uint32_t*>(&h2);
    lo = *reinterpret_cast<uint32_t*>(&l2);
}

// ---------------- x conversion: [hi|lo|hi] bf16 ----------------
__global__ __launch_bounds__(256) void cvt_x(
    const float* __restrict__ in, __nv_bfloat16* __restrict__ out)
{
    int idx = blockIdx.x * 256 + threadIdx.x;
    int r = idx >> 8;
    int c = (idx & 255) << 2;
    float4 v = *reinterpret_cast<const float4*>(in + (size_t)r * E_ + c);
    uint32_t h0, l0, h1, l1;
    pack_hl(v.x, v.y, h0, l0);
    pack_hl(v.z, v.w, h1, l1);
    uint32_t* o = reinterpret_cast<uint32_t*>(out + (size_t)r * K3_);
    int cw = c >> 1;
    o[cw] = h0; o[cw + 1] = h1;
    o[512 + cw] = l0; o[512 + cw + 1] = l1;
    o[1024 + cw] = h0; o[1024 + cw + 1] = h1;
}

// ---------------- weight conversion (4 fused): [hi|hi|lo] bf16 ----------------
__global__ __launch_bounds__(256) void cvt_w4(
    const float* __restrict__ W0, const float* __restrict__ W1,
    const float* __restrict__ W2, const float* __restrict__ W3,
    __nv_bfloat16* __restrict__ O0, __nv_bfloat16* __restrict__ O1,
    __nv_bfloat16* __restrict__ O2, __nv_bfloat16* __restrict__ O3)
{
    int sel = blockIdx.y;
    const float* in = sel == 0 ? W0 : sel == 1 ? W1 : sel == 2 ? W2 : W3;
    __nv_bfloat16* out = sel == 0 ? O0 : sel == 1 ? O1 : sel == 2 ? O2 : O3;
    int idx = blockIdx.x * 256 + threadIdx.x;
    int r = idx >> 8;
    int c = (idx & 255) << 2;
    float4 v = *reinterpret_cast<const float4*>(in + (size_t)r * E_ + c);
    uint32_t h0, l0, h1, l1;
    pack_hl(v.x, v.y, h0, l0);
    pack_hl(v.z, v.w, h1, l1);
    uint32_t* o = reinterpret_cast<uint32_t*>(out + (size_t)r * K3_);
    int cw = c >> 1;
    o[cw] = h0; o[cw + 1] = h1;
    o[512 + cw] = h0;  o[512 + cw + 1] = h1;
    o[1024 + cw] = l0; o[1024 + cw + 1] = l1;
}

// ---------------- HMMA NT GEMM (bf16, ldmatrix), 4-stage, 2 CTAs/SM ----------------
#define GS_W 20
#define G_STAGE_W (256 * GS_W)
#define G_SMEM_BYTES (4 * G_STAGE_W * 4)

template<int SPLIT>
__global__ __launch_bounds__(256, 2) void gemm_mma_t(
    const __nv_bfloat16* __restrict__ A,
    const __nv_bfloat16* __restrict__ W0, const __nv_bfloat16* __restrict__ W1,
    const __nv_bfloat16* __restrict__ W2,
    const float* __restrict__ b0, const float* __restrict__ b1, const float* __restrict__ b2,
    float* __restrict__ Cf,
    __half* __restrict__ S0, __half* __restrict__ S1, __half* __restrict__ S2)
{
    extern __shared__ uint32_t smw[];
    const int z = blockIdx.z;
    const __nv_bfloat16* W = (z == 0) ? W0 : (z == 1) ? W1 : W2;
    const float* bias = (z == 0) ? b0 : (z == 1) ? b1 : b2;
    __half* Sp = (z == 0) ? S0 : (z == 1) ? S1 : S2;

    const int tid = threadIdx.x;
    const int wid = tid >> 5, lane = tid & 31;
    const int g = lane >> 2, t4 = lane & 3;
    const int wm = wid & 3, wn = wid >> 2;
    const int m0 = blockIdx.y * 128;
    const int n0 = blockIdx.x * 128;
    const int NT = K3_ / 32;
    const uint32_t smb = smem_u32(smw);

    auto issue = [&](int kt) {
        const int sb = (kt & 3) * G_STAGE_W;
#pragma unroll
        for (int u = 0; u < 2; u++) {
            int c = tid + 256 * u;
            int row = c >> 2, k4 = c & 3;
            uint32_t sa = smb + (sb + row * GS_W + k4 * 4) * 4;
            cp_async16(sa, A + (size_t)(m0 + row) * K3_ + kt * 32 + k4 * 8);
            cp_async16(sa + 128 * GS_W * 4, W + (size_t)(n0 + row) * K3_ + kt * 32 + k4 * 8);
        }
        cp_commit();
    };

    float acc[2][8][4];
#pragma unroll
    for (int i = 0; i < 2; i++)
#pragma unroll
        for (int j = 0; j < 8; j++)
#pragma unroll
            for (int q = 0; q < 4; q++) acc[i][j][q] = 0.0f;

    issue(0); issue(1); issue(2);

    const int a_row = 32 * wm + (lane & 15);
    const int a_cw  = 4 * (lane >> 4);
    const int b_row = 64 * wn + (lane & 7) + 8 * (lane >> 4);
    const int b_cw  = 4 * ((lane >> 3) & 1);

    for (int kt = 0; kt < NT; kt++) {
        if (kt < NT - 2)       asm volatile("cp.async.wait_group 2;" ::: "memory");
        else if (kt == NT - 2) asm volatile("cp.async.wait_group 1;" ::: "memory");
        else                   asm volatile("cp.async.wait_group 0;" ::: "memory");
        __syncthreads();
        if (kt + 3 < NT) issue(kt + 3);

        const int sb = (kt & 3) * G_STAGE_W;
        const int bb = sb + 128 * GS_W;
#pragma unroll
        for (int kk = 0; kk < 2; kk++) {
            uint32_t a[2][4], b[8][2];
#pragma unroll
            for (int i = 0; i < 2; i++)
                ldsm4(a[i], smb + (sb + (a_row + 16 * i) * GS_W + a_cw + 8 * kk) * 4);
#pragma unroll
            for (int jp = 0; jp < 4; jp++) {
                uint32_t r4[4];
                ldsm4(r4, smb + (bb + (b_row + 16 * jp) * GS_W + b_cw + 8 * kk) * 4);
                b[2 * jp][0] = r4[0]; b[2 * jp][1] = r4[1];
                b[2 * jp + 1][0] = r4[2]; b[2 * jp + 1][1] = r4[3];
            }
#pragma unroll
            for (int i = 0; i < 2; i++)
#pragma unroll
                for (int j = 0; j < 8; j++) mma16816(acc[i][j], a[i], b[j]);
        }
    }

    if (SPLIT) {
        const int head = (n0 + 64 * wn) >> 6;
        uint32_t* outw = reinterpret_cast<uint32_t*>(Sp);
#pragma unroll
        for (int i = 0; i < 2; i++) {
            int row = m0 + 32 * wm + 16 * i + g;
#pragma unroll
            for (int j = 0; j < 8; j++) {
                int d = 8 * j + 2 * t4;
                float2 bb2 = *reinterpret_cast<const float2*>(bias + n0 + 64 * wn + d);
                uint32_t hi, lo;
                int w0 = row * 1024 + head * 64 + (d >> 1);
                pack_hl_f16(acc[i][j][0] + bb2.x, acc[i][j][1] + bb2.y, hi, lo);
                outw[w0] = hi; outw[w0 + 32] = lo;
                w0 += 8 * 1024;
                pack_hl_f16(acc[i][j][2] + bb2.x, acc[i][j][3] + bb2.y, hi, lo);
                outw[w0] = hi; outw[w0 + 32] = lo;
            }
        }
    } else {
#pragma unroll
        for (int i = 0; i < 2; i++) {
            int row = m0 + 32 * wm + 16 * i + g;
#pragma unroll
            for (int j = 0; j < 8; j++) {
                int col = n0 + 64 * wn + 8 * j + 2 * t4;
                float2 bb2 = *reinterpret_cast<const float2*>(bias + col);
                float2 v0 = { acc[i][j][0] + bb2.x, acc[i][j][1] + bb2.y };
                float2 v1 = { acc[i][j][2] + bb2.x, acc[i][j][3] + bb2.y };
                *reinterpret_cast<float2*>(Cf + (size_t)row * E_ + col) = v0;
                *reinterpret_cast<float2*>(Cf + (size_t)(row + 8) * E_ + col) = v1;
            }
        }
    }
}

// ---------------- Flash attention: fp16 2-term, 128 threads, 4 warps x m32 ----------------
// QT=128, KT=64. smem words:
//   Q: [0, 8704)  rows 0..127, stride 68: [hi 32w | lo 32w | pad 4w]
//   K: 2 bufs @ 8704, each 64 x 36 (hi only)
//   V: 2 bufs @ 13312, each 64 x 36 (hi only)
#define FQT 128
#define FKT 64
#define QS_W 68
#define KS_W 36
#define VS_W 36
#define KB0 8704
#define KBUF_W (64 * KS_W)            // 2304
#define VB0 (KB0 + 2 * KBUF_W)        // 13312
#define VBUF_W (64 * VS_W)            // 2304
#define F_SMEM_BYTES ((VB0 + 2 * VBUF_W) * 4)   // 71680

__global__ __launch_bounds__(128, 2) void flash_mma(
    const __half* __restrict__ Qg, const __half* __restrict__ Kg,
    const __half* __restrict__ Vg, uint32_t* __restrict__ Cw)
{
    extern __shared__ uint32_t smw[];
    const uint32_t smb = smem_u32(smw);
    const int tid = threadIdx.x;
    const int wid = tid >> 5, lane = tid & 31;
    const int g = lane >> 2, t4 = lane & 3;
    const int bz = blockIdx.z, hh = blockIdx.y;
    const int q0 = blockIdx.x * FQT;

    // ---- issue Q (hi+lo, one group): 2048 chunks / 128 thr ----
    {
        const char* qg = (const char*)Qg + ((size_t)(bz * N_ + q0) * 2048 + hh * 128) * 2;
#pragma unroll
        for (int u = 0; u < 16; u++) {
            int c = tid + 128 * u;
            int row = c >> 4, p = c & 15;
            cp_async16(smb + (row * QS_W + p * 4) * 4, qg + (size_t)row * 4096 + p * 16);
        }
        cp_commit();
    }
    // ---- issue K/V hi-only: 512 chunks each ----
    auto issue_kv = [&](int t) {
        const int b = t & 1;
        const char* kg = (const char*)Kg + ((size_t)(bz * N_ + t * 64) * 2048 + hh * 128) * 2;
        const char* vg = (const char*)Vg + ((size_t)(bz * N_ + t * 64) * 2048 + hh * 128) * 2;
#pragma unroll
        for (int u = 0; u < 4; u++) {
            int c = tid + 128 * u;
            int row = c >> 3, p = c & 7;
            cp_async16(smb + ((KB0 + b * KBUF_W) + row * KS_W + p * 4) * 4,
                       kg + (size_t)row * 4096 + p * 16);
        }
#pragma unroll
        for (int u = 0; u < 4; u++) {
            int c = tid + 128 * u;
            int row = c >> 3, p = c & 7;
            cp_async16(smb + ((VB0 + b * VBUF_W) + row * VS_W + p * 4) * 4,
                       vg + (size_t)row * 4096 + p * 16);
        }
        cp_commit();
    };

    issue_kv(0);
    asm volatile("cp.async.wait_group 1;" ::: "memory");   // Q resident
    __syncthreads();

    // ---- hoist Q-hi fragments ----
    const int qa_row = 32 * wid + (lane & 15);
    const int qa_cw  = 4 * (lane >> 4);
    uint32_t qh[2][4][4];
#pragma unroll
    for (int i = 0; i < 2; i++)
#pragma unroll
        for (int kc = 0; kc < 4; kc++)
            ldsm4(qh[i][kc], smb + ((qa_row + 16 * i) * QS_W + qa_cw + 8 * kc) * 4);

    float o[2][8][4], mrow[2][2], lrow[2][2];
#pragma unroll
    for (int i = 0; i < 2; i++) {
        mrow[i][0] = mrow[i][1] = -CUDART_INF_F;
        lrow[i][0] = lrow[i][1] = 0.0f;
#pragma unroll
        for (int j = 0; j < 8; j++)
#pragma unroll
            for (int q = 0; q < 4; q++) o[i][j][q] = 0.0f;
    }

    const int kb_row = (lane & 7) + 8 * (lane >> 4);
    const int kb_cw  = 4 * ((lane >> 3) & 1);
    const int tsel = lane >> 3;

    for (int t = 0; t < N_ / FKT; t++) {
        if (t + 1 < N_ / FKT) {
            issue_kv(t + 1);
            asm volatile("cp.async.wait_group 1;" ::: "memory");
        } else {
            asm volatile("cp.async.wait_group 0;" ::: "memory");
        }
        __syncthreads();
        const int koff = KB0 + (t & 1) * KBUF_W;
        const int voff = VB0 + (t & 1) * VBUF_W;

        // ---- S = (Qh + Ql) Kh : 2 passes per kc ----
        float s[2][8][4];
#pragma unroll
        for (int i = 0; i < 2; i++)
#pragma unroll
            for (int j = 0; j < 8; j++)
#pragma unroll
                for (int q = 0; q < 4; q++) s[i][j][q] = 0.0f;

#pragma unroll
        for (int kc = 0; kc < 4; kc++) {
            uint32_t kb[8][2];
#pragma unroll
            for (int jp = 0; jp < 4; jp++) {
                uint32_t r4[4];
                ldsm4(r4, smb + (koff + (kb_row + 16 * jp) * KS_W + kb_cw + 8 * kc) * 4);
                kb[2 * jp][0] = r4[0]; kb[2 * jp][1] = r4[1];
                kb[2 * jp + 1][0] = r4[2]; kb[2 * jp + 1][1] = r4[3];
            }
#pragma unroll
            for (int i = 0; i < 2; i++)
#pragma unroll
                for (int j = 0; j < 8; j++) mma16816f(s[i][j], qh[i][kc], kb[j]);
            uint32_t ql[2][4];
#pragma unroll
            for (int i = 0; i < 2; i++)
                ldsm4(ql[i], smb + ((qa_row + 16 * i) * QS_W + 32 + qa_cw + 8 * kc) * 4);
#pragma unroll
            for (int i = 0; i < 2; i++)
#pragma unroll
                for (int j = 0; j < 8; j++) mma16816f(s[i][j], ql[i], kb[j]);
        }

        // ---- online softmax ----
#pragma unroll
        for (int i = 0; i < 2; i++) {
#pragma unroll
            for (int h = 0; h < 2; h++) {
                float mx = -CUDART_INF_F;
#pragma unroll
                for (int j = 0; j < 8; j++)
                    mx = fmaxf(mx, fmaxf(s[i][j][2 * h], s[i][j][2 * h + 1]));
                mx = fmaxf(mx, __shfl_xor_sync(0xFFFFFFFFu, mx, 1));
                mx = fmaxf(mx, __shfl_xor_sync(0xFFFFFFFFu, mx, 2));
                float mnew = fmaxf(mrow[i][h], mx);
                float alpha = __expf(mrow[i][h] - mnew);
                mrow[i][h] = mnew;
                float ls = 0.0f;
#pragma unroll
                for (int j = 0; j < 8; j++) {
                    float p0 = __expf(s[i][j][2 * h] - mnew);
                    float p1 = __expf(s[i][j][2 * h + 1] - mnew);
                    ls += p0 + p1;
                    s[i][j][2 * h] = p0; s[i][j][2 * h + 1] = p1;
                }
                ls += __shfl_xor_sync(0xFFFFFFFFu, ls, 1);
                ls += __shfl_xor_sync(0xFFFFFFFFu, ls, 2);
                lrow[i][h] = lrow[i][h] * alpha + ls;
#pragma unroll
                for (int j = 0; j < 8; j++) {
                    o[i][j][2 * h] *= alpha; o[i][j][2 * h + 1] *= alpha;
                }
            }
        }

        // ---- PV: (Ph + Pl) Vh : per-kc pack + 2 passes ----
#pragma unroll
        for (int kc = 0; kc < 4; kc++) {
            uint32_t ph[2][2], phB[2][2], pl[2][2], plB[2][2];
#pragma unroll
            for (int i = 0; i < 2; i++)
#pragma unroll
                for (int jj = 0; jj < 2; jj++) {
                    int j = 2 * kc + jj;
                    pack_hl_f16(s[i][j][0], s[i][j][1], ph[i][jj], pl[i][jj]);
                    pack_hl_f16(s[i][j][2], s[i][j][3], phB[i][jj], plB[i][jj]);
                }
            uint32_t vb[8][2];
#pragma unroll
            for (int jj = 0; jj < 8; jj += 2) {
                uint32_t r4[4];
                int row = 16 * kc + 8 * (tsel & 1) + (lane & 7);
                ldsm4t(r4, smb + (voff + row * VS_W) * 4 + 16 * (jj + (tsel >> 1)));
                vb[jj][0] = r4[0]; vb[jj][1] = r4[1];
                vb[jj + 1][0] = r4[2]; vb[jj + 1][1] = r4[3];
            }
#pragma unroll
            for (int i = 0; i < 2; i++) {
                uint32_t pa[4] = { ph[i][0], phB[i][0], ph[i][1], phB[i][1] };
#pragma unroll
                for (int j = 0; j < 8; j++) mma16816f(o[i][j], pa, vb[j]);
            }
#pragma unroll
            for (int i = 0; i < 2; i++) {
                uint32_t pa[4] = { pl[i][0], plB[i][0], pl[i][1], plB[i][1] };
#pragma unroll
                for (int j = 0; j < 8; j++) mma16816f(o[i][j], pa, vb[j]);
            }
        }
        __syncthreads();
    }

    // ---- epilogue: write bf16 split context into [hi|lo|hi] ----
#pragma unroll
    for (int i = 0; i < 2; i++) {
        float inv0 = 1.0f / (lrow[i][0] * 32.0f);
        float inv1 = 1.0f / (lrow[i][1] * 32.0f);
        int row = bz * N_ + q0 + 32 * wid + 16 * i + g;
#pragma unroll
        for (int j = 0; j < 8; j++) {
            int cw = (hh * 64 + 8 * j + 2 * t4) >> 1;
            uint32_t hi, lo;
            int base = row * 1536;
            pack_hl(o[i][j][0] * inv0, o[i][j][1] * inv0, hi, lo);
            Cw[base + cw] = hi; Cw[base + 512 + cw] = lo; Cw[base + 1024 + cw] = hi;
            base = (row + 8) * 1536;
            pack_hl(o[i][j][2] * inv1, o[i][j][3] * inv1, hi, lo);
            Cw[base + cw] = hi; Cw[base + 512 + cw] = lo; Cw[base + 1024 + cw] = hi;
        }
    }
}

// ---------------- launcher ----------------
extern "C" void kernel_launch(void* const* d_in, const int* in_sizes, int n_in,
                              void* d_out, int out_size)
{
    const float* x  = (const float*)d_in[0];
    const float* Wq = (const float*)d_in[1];
    const float* bq = (const float*)d_in[2];
    const float* Wk = (const float*)d_in[3];
    const float* bk = (const float*)d_in[4];
    const float* Wv = (const float*)d_in[5];
    const float* bv = (const float*)d_in[6];
    const float* Wo = (const float*)d_in[7];
    const float* bo = (const float*)d_in[8];
    float* out = (float*)d_out;

    cudaFuncSetAttribute(gemm_mma_t<1>, cudaFuncAttributeMaxDynamicSharedMemorySize, G_SMEM_BYTES);
    cudaFuncSetAttribute(gemm_mma_t<0>, cudaFuncAttributeMaxDynamicSharedMemorySize, G_SMEM_BYTES);
    cudaFuncSetAttribute(flash_mma, cudaFuncAttributeMaxDynamicSharedMemorySize, F_SMEM_BYTES);

    __half *Qs, *Ks, *Vs;
    __nv_bfloat16 *xe, *ce, *wqe, *wke, *wve, *woe;
    cudaGetSymbolAddress((void**)&Qs, g_Qs);
    cudaGetSymbolAddress((void**)&Ks, g_Ks);
    cudaGetSymbolAddress((void**)&Vs, g_Vs);
    cudaGetSymbolAddress((void**)&xe, g_xext);
    cudaGetSymbolAddress((void**)&ce, g_cext);
    cudaGetSymbolAddress((void**)&wqe, g_wqext);
    cudaGetSymbolAddress((void**)&wke, g_wkext);
    cudaGetSymbolAddress((void**)&wve, g_wvext);
    cudaGetSymbolAddress((void**)&woe, g_woext);

    cvt_x<<<M_, 256>>>(x, xe);
    dim3 wgrid(E_, 4);
    cvt_w4<<<wgrid, 256>>>(Wq, Wk, Wv, Wo, wqe, wke, wve, woe);

    dim3 ggrid3(E_ / 128, M_ / 128, 3);
    gemm_mma_t<1><<<ggrid3, 256, G_SMEM_BYTES>>>(
        xe, wqe, wke, wve, bq, bk, bv, nullptr, Qs, Ks, Vs);

    dim3 fgrid(N_ / FQT, H_, B_);
    flash_mma<<<fgrid, 128, F_SMEM_BYTES>>>(Qs, Ks, Vs, (uint32_t*)ce);

    dim3 ggrid1(E_ / 128, M_ / 128, 1);
    gemm_mma_t<0><<<ggrid1, 256, G_SMEM_BYTES>>>(
        ce, woe, woe, woe, bo, bo, bo, out, nullptr, nullptr, nullptr);
}